// round 15
// baseline (speedup 1.0000x reference)
#include <cuda_runtime.h>
#include <cuda_bf16.h>
#include <math.h>

#define Dm 768
#define Hh 12
#define DEPTH 12
#define WARM 2
#define Kk 64
#define MLPD 3072
#define NTOK 197
#define NSEL 65
#define Bb 32
#define NREF (DEPTH - WARM)

// ---------------- scratch (device globals; no allocation) ----------------
__device__ __align__(16) float g_X[Bb * NTOK * Dm];
__device__ __align__(16) float g_Hbuf[Bb * NTOK * Dm];      // patch out / refined tf32 act
__device__ __align__(16) float g_QKV[Bb * NTOK * 3 * Dm];
__device__ float g_scores[Bb * NTOK];
__device__ int   g_idx[Bb * NSEL];
__device__ __align__(16) float g_Xr[Bb * NSEL * Dm];
__device__ __align__(16) float g_F1f[Bb * NSEL * MLPD];     // refined fc1 out (tf32, K-permuted)

__device__ __align__(16) __nv_bfloat16 g_Ah[Bb * NTOK * Dm];
__device__ __align__(16) __nv_bfloat16 g_Al[Bb * NTOK * Dm];
__device__ __align__(16) __nv_bfloat16 g_F1h[Bb * NTOK * MLPD];
__device__ __align__(16) __nv_bfloat16 g_F1l[Bb * NTOK * MLPD];

__device__ __align__(16) __nv_bfloat16 g_Wqkvh[WARM * 2304 * 768];
__device__ __align__(16) __nv_bfloat16 g_Wqkvl[WARM * 2304 * 768];
__device__ __align__(16) __nv_bfloat16 g_Wprojh[WARM * 768 * 768];
__device__ __align__(16) __nv_bfloat16 g_Wprojl[WARM * 768 * 768];
__device__ __align__(16) __nv_bfloat16 g_W1h[WARM * 3072 * 768];
__device__ __align__(16) __nv_bfloat16 g_W1l[WARM * 3072 * 768];
__device__ __align__(16) __nv_bfloat16 g_W2h[WARM * 768 * 3072];
__device__ __align__(16) __nv_bfloat16 g_W2l[WARM * 768 * 3072];
__device__ __align__(16) __nv_bfloat16 g_PWh[768 * 768];
__device__ __align__(16) __nv_bfloat16 g_PWl[768 * 768];

// refined tf32 weights (transposed [N,K], f32 containers, tf32-rounded, K-permuted)
__device__ __align__(16) float g_W32q[NREF * 2304 * 768];
__device__ __align__(16) float g_W32p[NREF * 768 * 768];
__device__ __align__(16) float g_W32f1[NREF * 3072 * 768];
__device__ __align__(16) float g_W32f2[NREF * 768 * 3072];

// ---------------- helpers ----------------
__device__ __forceinline__ float gelu_exact(float x) {
    return 0.5f * x * (1.0f + erff(x * 0.70710678118654752440f));
}
__device__ __forceinline__ float warp_sum(float v) {
    #pragma unroll
    for (int o = 16; o; o >>= 1) v += __shfl_xor_sync(0xFFFFFFFFu, v, o);
    return v;
}
__device__ __forceinline__ float warp_max(float v) {
    #pragma unroll
    for (int o = 16; o; o >>= 1) v = fmaxf(v, __shfl_xor_sync(0xFFFFFFFFu, v, o));
    return v;
}
__device__ __forceinline__ void split_store(__nv_bfloat16* ph, __nv_bfloat16* pl, float v) {
    __nv_bfloat16 hv = __float2bfloat16(v);
    *ph = hv;
    *pl = __float2bfloat16(v - __bfloat162float(hv));
}
__device__ __forceinline__ float to_tf32(float x) {
    unsigned u;
    asm("cvt.rna.tf32.f32 %0, %1;" : "=r"(u) : "f"(x));
    return __uint_as_float(u);
}
// K-label permutation within 8-groups: order [0,4,1,5,2,6,3,7]
__device__ __forceinline__ int permk(int k) {
    return (k & ~7) | (((k & 3) << 1) | ((k >> 2) & 1));
}
__device__ __forceinline__ unsigned smem_u32(const void* p) {
    unsigned a;
    asm("{ .reg .u64 t; cvta.to.shared.u64 t, %1; cvt.u32.u64 %0, t; }" : "=r"(a) : "l"(p));
    return a;
}
__device__ __forceinline__ void cp16(unsigned dst, const void* src, bool pred) {
    int sz = pred ? 16 : 0;
    asm volatile("cp.async.cg.shared.global [%0], [%1], 16, %2;\n"
                 :: "r"(dst), "l"(src), "r"(sz));
}
__device__ __forceinline__ void cp16ca(unsigned dst, const void* src, bool pred) {
    int sz = pred ? 16 : 0;
    asm volatile("cp.async.ca.shared.global [%0], [%1], 16, %2;\n"
                 :: "r"(dst), "l"(src), "r"(sz));
}
__device__ __forceinline__ void cp_commit() {
    asm volatile("cp.async.commit_group;\n" ::);
}
template<int NG>
__device__ __forceinline__ void cp_wait() {
    asm volatile("cp.async.wait_group %0;\n" :: "n"(NG));
}
__device__ __forceinline__ void ldsm4(unsigned* r, unsigned a) {
    asm volatile("ldmatrix.sync.aligned.m8n8.x4.shared.b16 {%0,%1,%2,%3}, [%4];\n"
                 : "=r"(r[0]), "=r"(r[1]), "=r"(r[2]), "=r"(r[3]) : "r"(a));
}
__device__ __forceinline__ void mma16816(float* c, const unsigned* a, const unsigned* b) {
    asm volatile(
        "mma.sync.aligned.m16n8k16.row.col.f32.bf16.bf16.f32 "
        "{%0,%1,%2,%3}, {%4,%5,%6,%7}, {%8,%9}, {%0,%1,%2,%3};\n"
        : "+f"(c[0]), "+f"(c[1]), "+f"(c[2]), "+f"(c[3])
        : "r"(a[0]), "r"(a[1]), "r"(a[2]), "r"(a[3]), "r"(b[0]), "r"(b[1]));
}
__device__ __forceinline__ void mma16808tf(float* c, const unsigned* a, const unsigned* b) {
    asm volatile(
        "mma.sync.aligned.m16n8k8.row.col.f32.tf32.tf32.f32 "
        "{%0,%1,%2,%3}, {%4,%5,%6,%7}, {%8,%9}, {%0,%1,%2,%3};\n"
        : "+f"(c[0]), "+f"(c[1]), "+f"(c[2]), "+f"(c[3])
        : "r"(a[0]), "r"(a[1]), "r"(a[2]), "r"(a[3]), "r"(b[0]), "r"(b[1]));
}

// ================= split-bf16 mma.sync GEMM, 64x64 tiles (warm + patch) =========
#define LDT 72
#define TILE64 (64 * LDT * 2)
#define STAGE64 (4 * TILE64)

__device__ __forceinline__ void load_stage(unsigned sbuf,
                                           const __nv_bfloat16* __restrict__ Sa_h,
                                           const __nv_bfloat16* __restrict__ Sa_l,
                                           const __nv_bfloat16* __restrict__ Sb_h,
                                           const __nv_bfloat16* __restrict__ Sb_l,
                                           int rowA, int Mlim, int rowB, int Nlim,
                                           int ldK, int k0, int tid) {
    const int ch = tid & 7, rr = tid >> 3;
    #pragma unroll
    for (int j = 0; j < 4; j++) {
        int r = j * 16 + rr;
        unsigned doff = (unsigned)(r * (LDT * 2) + ch * 16);
        {
            int gr = rowA + r;
            bool ok = gr < Mlim;
            int cr = ok ? gr : (Mlim - 1);
            size_t so = (size_t)cr * ldK + k0 + ch * 8;
            cp16(sbuf + doff, Sa_h + so, ok);
            cp16(sbuf + TILE64 + doff, Sa_l + so, ok);
        }
        {
            int gb = rowB + r;
            bool ok = gb < Nlim;
            int cb = ok ? gb : (Nlim - 1);
            size_t so = (size_t)cb * ldK + k0 + ch * 8;
            cp16ca(sbuf + 2 * TILE64 + doff, Sb_h + so, ok);
            cp16ca(sbuf + 3 * TILE64 + doff, Sb_l + so, ok);
        }
    }
}

template<int EPI>   // 0 bias; 1 bias+res; 2 bias+GELU->bf16 pair
__global__ void __launch_bounds__(128, 3)
bgemm_kernel(const __nv_bfloat16* __restrict__ Ah, const __nv_bfloat16* __restrict__ Al,
             const __nv_bfloat16* __restrict__ Bh, const __nv_bfloat16* __restrict__ Bl,
             const float* __restrict__ bias, const float* __restrict__ Cin,
             float* __restrict__ outF, __nv_bfloat16* __restrict__ outBh,
             __nv_bfloat16* __restrict__ outBl, int M, int N, int K) {
    extern __shared__ char smv[];
    const int tid = threadIdx.x;
    const int wid = tid >> 5, lane = tid & 31;
    const int blockRow = blockIdx.y << 6;
    const int blockCol = blockIdx.x << 6;
    const int wm = (wid >> 1) << 5;
    const int wn = (wid & 1) << 5;
    const unsigned sb = smem_u32(smv);

    float acc[2][4][4];
    #pragma unroll
    for (int i = 0; i < 2; i++)
        #pragma unroll
        for (int j = 0; j < 4; j++) {
            acc[i][j][0] = 0.f; acc[i][j][1] = 0.f; acc[i][j][2] = 0.f; acc[i][j][3] = 0.f;
        }

    const int T = K >> 6;
    load_stage(sb, Ah, Al, Bh, Bl, blockRow, M, blockCol, N, K, 0, tid);
    cp_commit();

    const int arow = (lane & 15);
    const int kofA = (lane >> 4) << 3;
    const int brow = ((lane >> 4) << 3) + (lane & 7);
    const int kofB = lane & 8;

    for (int kt = 0; kt < T; kt++) {
        if (kt + 1 < T) {
            load_stage(sb + (unsigned)((kt + 1) & 1) * STAGE64, Ah, Al, Bh, Bl,
                       blockRow, M, blockCol, N, K, (kt + 1) << 6, tid);
            cp_commit();
            cp_wait<1>();
        } else {
            cp_wait<0>();
        }
        __syncthreads();

        const unsigned bufb = sb + (unsigned)(kt & 1) * STAGE64;
        const unsigned aB = bufb + (unsigned)((wm + arow) * (LDT * 2));
        const unsigned bB = bufb + 2 * TILE64 + (unsigned)((wn + brow) * (LDT * 2));
        #pragma unroll
        for (int ks = 0; ks < 4; ks++) {
            const int kk = ks << 4;
            unsigned ah[2][4], al[2][4], bh[4][2], bl[4][2];
            #pragma unroll
            for (int mi = 0; mi < 2; mi++) {
                unsigned ad = aB + (unsigned)(mi * 16 * (LDT * 2) + (kk + kofA) * 2);
                ldsm4(ah[mi], ad);
                ldsm4(al[mi], ad + TILE64);
            }
            #pragma unroll
            for (int nj = 0; nj < 2; nj++) {
                unsigned bd = bB + (unsigned)(nj * 16 * (LDT * 2) + (kk + kofB) * 2);
                unsigned t0[4], t1[4];
                ldsm4(t0, bd);
                ldsm4(t1, bd + TILE64);
                bh[nj * 2][0] = t0[0]; bh[nj * 2][1] = t0[1];
                bh[nj * 2 + 1][0] = t0[2]; bh[nj * 2 + 1][1] = t0[3];
                bl[nj * 2][0] = t1[0]; bl[nj * 2][1] = t1[1];
                bl[nj * 2 + 1][0] = t1[2]; bl[nj * 2 + 1][1] = t1[3];
            }
            #pragma unroll
            for (int mi = 0; mi < 2; mi++)
                #pragma unroll
                for (int ni = 0; ni < 4; ni++) {
                    mma16816(acc[mi][ni], ah[mi], bh[ni]);
                    mma16816(acc[mi][ni], ah[mi], bl[ni]);
                    mma16816(acc[mi][ni], al[mi], bh[ni]);
                }
        }
        __syncthreads();
    }

    const int gid = lane >> 2, tig = lane & 3;
    #pragma unroll
    for (int mi = 0; mi < 2; mi++) {
        #pragma unroll
        for (int ni = 0; ni < 4; ni++) {
            const int gr0 = blockRow + wm + mi * 16 + gid;
            const int gc = blockCol + wn + ni * 8 + tig * 2;
            const float b0v = bias[gc], b1v = bias[gc + 1];
            #pragma unroll
            for (int hf = 0; hf < 2; hf++) {
                const int gr = gr0 + hf * 8;
                if (gr < M) {
                    float v0 = acc[mi][ni][hf * 2 + 0] + b0v;
                    float v1 = acc[mi][ni][hf * 2 + 1] + b1v;
                    if (EPI == 1) {
                        const float2 rv = *(const float2*)(Cin + (size_t)gr * N + gc);
                        v0 += rv.x; v1 += rv.y;
                    }
                    if (EPI == 2) {
                        v0 = gelu_exact(v0); v1 = gelu_exact(v1);
                        __nv_bfloat16 h0 = __float2bfloat16(v0);
                        __nv_bfloat16 h1 = __float2bfloat16(v1);
                        __nv_bfloat162 hp; hp.x = h0; hp.y = h1;
                        __nv_bfloat162 lp;
                        lp.x = __float2bfloat16(v0 - __bfloat162float(h0));
                        lp.y = __float2bfloat16(v1 - __bfloat162float(h1));
                        *(__nv_bfloat162*)(outBh + (size_t)gr * N + gc) = hp;
                        *(__nv_bfloat162*)(outBl + (size_t)gr * N + gc) = lp;
                    } else {
                        float2 o; o.x = v0; o.y = v1;
                        *(float2*)(outF + (size_t)gr * N + gc) = o;
                    }
                }
            }
        }
    }
}

// ================= single-MMA tf32 GEMM, 64x64 tiles, permuted-K float2 loads =========
#define LDF 72
#define TILEF (64 * LDF * 4)       // 18432 B
#define STAGEF (2 * TILEF)         // 36864 B

__device__ __forceinline__ void load_stage_f(unsigned sbuf,
                                             const float* __restrict__ Af,
                                             const float* __restrict__ Bf,
                                             int rowA, int Mlim, int rowB, int Nlim,
                                             int ldK, int k0, int tid) {
    #pragma unroll
    for (int i = 0; i < 8; i++) {
        int idx = tid + i * 128;
        int r = idx >> 4, ch = idx & 15;
        unsigned doff = (unsigned)(r * (LDF * 4) + ch * 16);
        {
            int gr = rowA + r;
            bool ok = gr < Mlim;
            int cr = ok ? gr : (Mlim - 1);
            cp16(sbuf + doff, Af + (size_t)cr * ldK + k0 + ch * 4, ok);
        }
        {
            int gb = rowB + r;
            bool ok = gb < Nlim;
            int cb = ok ? gb : (Nlim - 1);
            cp16ca(sbuf + TILEF + doff, Bf + (size_t)cb * ldK + k0 + ch * 4, ok);
        }
    }
}

template<int EPI>   // 0 bias->f32; 1 bias+res->f32; 2 bias+GELU->tf32 f32 (K-permuted out)
__global__ void __launch_bounds__(128, 3)
tfgemm_kernel(const float* __restrict__ A, const float* __restrict__ B,
              const float* __restrict__ bias, const float* __restrict__ Cin,
              float* __restrict__ outF, int M, int N, int K) {
    extern __shared__ char smv[];
    const int tid = threadIdx.x;
    const int wid = tid >> 5, lane = tid & 31;
    const int blockRow = blockIdx.y << 6;
    const int blockCol = blockIdx.x << 6;
    const int wm = (wid >> 1) << 5;
    const int wn = (wid & 1) << 5;
    const unsigned sb = smem_u32(smv);
    const float2* sm2 = (const float2*)smv;

    float acc[2][4][4];
    #pragma unroll
    for (int i = 0; i < 2; i++)
        #pragma unroll
        for (int j = 0; j < 4; j++) {
            acc[i][j][0] = 0.f; acc[i][j][1] = 0.f; acc[i][j][2] = 0.f; acc[i][j][3] = 0.f;
        }

    const int T = K >> 6;
    load_stage_f(sb, A, B, blockRow, M, blockCol, N, K, 0, tid);
    cp_commit();

    const int gid = lane >> 2, tig = lane & 3;

    for (int kt = 0; kt < T; kt++) {
        if (kt + 1 < T) {
            load_stage_f(sb + (unsigned)((kt + 1) & 1) * STAGEF, A, B,
                         blockRow, M, blockCol, N, K, (kt + 1) << 6, tid);
            cp_commit();
            cp_wait<1>();
        } else {
            cp_wait<0>();
        }
        __syncthreads();

        // float2 units: stage offset, B-tile offset, row stride LDF/2 = 36
        const unsigned bufw2 = (unsigned)(kt & 1) * (STAGEF / 8);
        #pragma unroll
        for (int ks = 0; ks < 8; ks++) {
            const int kk2 = ks << 2;   // k/2
            unsigned af[2][4], bf[4][2];
            #pragma unroll
            for (int mi = 0; mi < 2; mi++) {
                unsigned r0 = bufw2 + (unsigned)((wm + mi * 16 + gid) * 36 + kk2 + tig);
                float2 alo = sm2[r0];             // rows gid   : (k+tig, k+tig+4)
                float2 ahi = sm2[r0 + 4 * LDF];   // rows gid+8
                af[mi][0] = __float_as_uint(alo.x);
                af[mi][2] = __float_as_uint(alo.y);
                af[mi][1] = __float_as_uint(ahi.x);
                af[mi][3] = __float_as_uint(ahi.y);
            }
            #pragma unroll
            for (int ni = 0; ni < 4; ni++) {
                unsigned rb = bufw2 + (unsigned)(TILEF / 8) +
                              (unsigned)((wn + ni * 8 + gid) * 36 + kk2 + tig);
                float2 bv = sm2[rb];
                bf[ni][0] = __float_as_uint(bv.x);
                bf[ni][1] = __float_as_uint(bv.y);
            }
            #pragma unroll
            for (int mi = 0; mi < 2; mi++)
                #pragma unroll
                for (int ni = 0; ni < 4; ni++)
                    mma16808tf(acc[mi][ni], af[mi], bf[ni]);
        }
        __syncthreads();
    }

    #pragma unroll
    for (int mi = 0; mi < 2; mi++) {
        #pragma unroll
        for (int ni = 0; ni < 4; ni++) {
            const int gr0 = blockRow + wm + mi * 16 + gid;
            const int gc = blockCol + wn + ni * 8 + tig * 2;
            const float b0v = bias[gc], b1v = bias[gc + 1];
            #pragma unroll
            for (int hf = 0; hf < 2; hf++) {
                const int gr = gr0 + hf * 8;
                if (gr < M) {
                    float v0 = acc[mi][ni][hf * 2 + 0] + b0v;
                    float v1 = acc[mi][ni][hf * 2 + 1] + b1v;
                    if (EPI == 1) {
                        const float2 rv = *(const float2*)(Cin + (size_t)gr * N + gc);
                        v0 += rv.x; v1 += rv.y;
                    }
                    if (EPI == 2) {
                        v0 = to_tf32(gelu_exact(v0));
                        v1 = to_tf32(gelu_exact(v1));
                        outF[(size_t)gr * N + permk(gc)]     = v0;
                        outF[(size_t)gr * N + permk(gc + 1)] = v1;
                    } else {
                        float2 o; o.x = v0; o.y = v1;
                        *(float2*)(outF + (size_t)gr * N + gc) = o;
                    }
                }
            }
        }
    }
}

// ---------------- weight converts ----------------
__global__ void convtrans_kernel(const float* __restrict__ W, __nv_bfloat16* __restrict__ Wh,
                                 __nv_bfloat16* __restrict__ Wl, int K, int N) {
    __shared__ float ts[32][33];
    const int l = blockIdx.z;
    const size_t off = (size_t)l * K * N;
    const int kb = blockIdx.y << 5, nb = blockIdx.x << 5;
    #pragma unroll
    for (int j = 0; j < 4; j++)
        ts[threadIdx.y + 8 * j][threadIdx.x] =
            W[off + (size_t)(kb + threadIdx.y + 8 * j) * N + nb + threadIdx.x];
    __syncthreads();
    const int tid = threadIdx.y * 32 + threadIdx.x;
    const int c2 = tid & 15, r0 = tid >> 4;
    #pragma unroll
    for (int j = 0; j < 2; j++) {
        int r = r0 + 16 * j;
        float v0 = ts[2 * c2][r], v1 = ts[2 * c2 + 1][r];
        __nv_bfloat16 h0 = __float2bfloat16(v0), h1 = __float2bfloat16(v1);
        __nv_bfloat162 hp; hp.x = h0; hp.y = h1;
        __nv_bfloat162 lp;
        lp.x = __float2bfloat16(v0 - __bfloat162float(h0));
        lp.y = __float2bfloat16(v1 - __bfloat162float(h1));
        size_t di = off + (size_t)(nb + r) * K + kb + 2 * c2;
        *(__nv_bfloat162*)(Wh + di) = hp;
        *(__nv_bfloat162*)(Wl + di) = lp;
    }
}

// tf32 transpose-convert with K-permutation
__global__ void convtrans_tf32_kernel(const float* __restrict__ W, float* __restrict__ Wt,
                                      int K, int N) {
    __shared__ float ts[32][33];
    const int l = blockIdx.z;
    const size_t off = (size_t)l * K * N;
    const int kb = blockIdx.y << 5, nb = blockIdx.x << 5;
    #pragma unroll
    for (int j = 0; j < 4; j++)
        ts[threadIdx.y + 8 * j][threadIdx.x] =
            W[off + (size_t)(kb + threadIdx.y + 8 * j) * N + nb + threadIdx.x];
    __syncthreads();
    const int tid = threadIdx.y * 32 + threadIdx.x;
    const int c2 = tid & 15, r0 = tid >> 4;
    #pragma unroll
    for (int j = 0; j < 2; j++) {
        int r = r0 + 16 * j;
        size_t rbase = off + (size_t)(nb + r) * K;
        Wt[rbase + permk(kb + 2 * c2)]     = to_tf32(ts[2 * c2][r]);
        Wt[rbase + permk(kb + 2 * c2 + 1)] = to_tf32(ts[2 * c2 + 1][r]);
    }
}

__global__ void conv_patchw_kernel(const float* __restrict__ W, __nv_bfloat16* __restrict__ Wh,
                                   __nv_bfloat16* __restrict__ Wl) {
    int i = blockIdx.x * 256 + threadIdx.x;
    if (i < 768 * 768 / 2) {
        float2 v = *(const float2*)(W + 2 * i);
        __nv_bfloat16 h0 = __float2bfloat16(v.x), h1 = __float2bfloat16(v.y);
        __nv_bfloat162 hp; hp.x = h0; hp.y = h1;
        __nv_bfloat162 lp;
        lp.x = __float2bfloat16(v.x - __bfloat162float(h0));
        lp.y = __float2bfloat16(v.y - __bfloat162float(h1));
        *(__nv_bfloat162*)(Wh + 2 * i) = hp;
        *(__nv_bfloat162*)(Wl + 2 * i) = lp;
    }
}

// ---------------- im2col / assemble ----------------
__global__ void im2col_kernel(const float* __restrict__ x, __nv_bfloat16* __restrict__ Ph,
                              __nv_bfloat16* __restrict__ Pl) {
    int t = blockIdx.x;
    int b = t / 196, p = t % 196;
    int py = p / 14, px = p % 14;
    for (int d = threadIdx.x; d < Dm; d += 256) {
        int c = d >> 8, r = (d >> 4) & 15, col = d & 15;
        float v = x[(((size_t)b * 3 + c) * 224 + py * 16 + r) * 224 + px * 16 + col];
        split_store(Ph + (size_t)t * Dm + d, Pl + (size_t)t * Dm + d, v);
    }
}

__global__ void assemble_kernel(const float* __restrict__ P, const float* __restrict__ cls,
                                const float* __restrict__ pos, float* __restrict__ X) {
    int t = blockIdx.x;
    int b = t / NTOK, n = t % NTOK;
    float* xr = X + (size_t)t * Dm;
    const float* pr = pos + (size_t)n * Dm;
    if (n == 0) {
        for (int d = threadIdx.x; d < Dm; d += 256) xr[d] = cls[d] + pr[d];
    } else {
        const float* pp = P + ((size_t)(b * 196 + n - 1)) * Dm;
        for (int d = threadIdx.x; d < Dm; d += 256) xr[d] = pp[d] + pr[d];
    }
}

// ---------------- LayerNorm variants ----------------
template<int TF>    // 0: bf16 hi/lo out ; 1: tf32 f32 out (K-permuted)
__global__ void ln_kernel(const float* __restrict__ X, const float* __restrict__ g,
                          const float* __restrict__ bt, __nv_bfloat16* __restrict__ Yh,
                          __nv_bfloat16* __restrict__ Yl, float* __restrict__ Yf) {
    __shared__ float red[8];
    __shared__ float stat[2];
    int t = blockIdx.x, tid = threadIdx.x;
    const float* xr = X + (size_t)t * Dm;
    float v0 = xr[tid], v1 = xr[tid + 256], v2 = xr[tid + 512];
    float s = warp_sum(v0 + v1 + v2);
    if ((tid & 31) == 0) red[tid >> 5] = s;
    __syncthreads();
    if (tid < 8) {
        float r = red[tid];
        #pragma unroll
        for (int o = 4; o; o >>= 1) r += __shfl_xor_sync(0xFFu, r, o);
        if (tid == 0) stat[0] = r * (1.f / 768.f);
    }
    __syncthreads();
    float m = stat[0];
    float d0 = v0 - m, d1 = v1 - m, d2 = v2 - m;
    float q = warp_sum(d0 * d0 + d1 * d1 + d2 * d2);
    if ((tid & 31) == 0) red[tid >> 5] = q;
    __syncthreads();
    if (tid < 8) {
        float r = red[tid];
        #pragma unroll
        for (int o = 4; o; o >>= 1) r += __shfl_xor_sync(0xFFu, r, o);
        if (tid == 0) stat[1] = rsqrtf(r * (1.f / 768.f) + 1e-6f);
    }
    __syncthreads();
    float rs = stat[1];
    size_t base = (size_t)t * Dm;
    float y0 = d0 * rs * g[tid]       + bt[tid];
    float y1 = d1 * rs * g[tid + 256] + bt[tid + 256];
    float y2 = d2 * rs * g[tid + 512] + bt[tid + 512];
    if (TF) {
        Yf[base + permk(tid)]       = to_tf32(y0);
        Yf[base + permk(tid + 256)] = to_tf32(y1);
        Yf[base + permk(tid + 512)] = to_tf32(y2);
    } else {
        split_store(Yh + base + tid,       Yl + base + tid,       y0);
        split_store(Yh + base + tid + 256, Yl + base + tid + 256, y1);
        split_store(Yh + base + tid + 512, Yl + base + tid + 512, y2);
    }
}

// ---------------- fused attention, 8 queries per warp ----------------
template<int NJ, int TF>
__global__ void __launch_bounds__(256)
attn_kernel(const float* __restrict__ QKV, __nv_bfloat16* __restrict__ Oh,
            __nv_bfloat16* __restrict__ Ol, float* __restrict__ Of, int N) {
    extern __shared__ float smf[];
    float* Ks = smf;
    float* Vs = Ks + N * 68;
    float* qs = Vs + N * 64;
    int b = blockIdx.x / Hh, hd = blockIdx.x % Hh;
    int tid = threadIdx.x, w = tid >> 5, lane = tid & 31;
    const float* base = QKV + (size_t)b * N * (3 * Dm);
    for (int idx = tid; idx < N * 64; idx += 256) {
        int n = idx >> 6, d = idx & 63;
        Ks[n * 68 + d] = base[(size_t)n * (3 * Dm) + Dm + hd * 64 + d];
        Vs[idx]        = base[(size_t)n * (3 * Dm) + 2 * Dm + hd * 64 + d];
    }
    __syncthreads();
    float* qw = qs + w * 512;
    for (int qt = w * 8; qt < N; qt += 64) {
        #pragma unroll
        for (int qi = 0; qi < 8; qi++) {
            int q = qt + qi;
            if (q < N) {
                const float* qp = base + (size_t)q * (3 * Dm) + hd * 64;
                qw[qi * 64 + lane]      = qp[lane]      * 0.125f;
                qw[qi * 64 + lane + 32] = qp[lane + 32] * 0.125f;
            }
        }
        __syncwarp();
        float s[8][NJ];
        #pragma unroll
        for (int qi = 0; qi < 8; qi++)
            #pragma unroll
            for (int jj = 0; jj < NJ; jj++) s[qi][jj] = -3e38f;
        #pragma unroll
        for (int jj = 0; jj < NJ; jj++) {
            int j = jj * 32 + lane;
            if (j < N) {
                const float4* k4 = (const float4*)(Ks + j * 68);
                float acc[8];
                #pragma unroll
                for (int qi = 0; qi < 8; qi++) acc[qi] = 0.f;
                #pragma unroll
                for (int d = 0; d < 16; d++) {
                    float4 kv = k4[d];
                    #pragma unroll
                    for (int qi = 0; qi < 8; qi++) {
                        float4 qv = ((const float4*)(qw + qi * 64))[d];
                        acc[qi] += qv.x * kv.x + qv.y * kv.y + qv.z * kv.z + qv.w * kv.w;
                    }
                }
                #pragma unroll
                for (int qi = 0; qi < 8; qi++) s[qi][jj] = acc[qi];
            }
        }
        float inv[8];
        #pragma unroll
        for (int qi = 0; qi < 8; qi++) {
            float m = -3e38f;
            #pragma unroll
            for (int jj = 0; jj < NJ; jj++) m = fmaxf(m, s[qi][jj]);
            m = warp_max(m);
            float sum = 0.f;
            #pragma unroll
            for (int jj = 0; jj < NJ; jj++) {
                float e = expf(s[qi][jj] - m);
                s[qi][jj] = e;
                sum += e;
            }
            sum = warp_sum(sum);
            inv[qi] = 1.f / sum;
        }
        float a0[8], a1[8];
        #pragma unroll
        for (int qi = 0; qi < 8; qi++) { a0[qi] = 0.f; a1[qi] = 0.f; }
        #pragma unroll
        for (int jj = 0; jj < NJ; jj++) {
            int jb = jj * 32;
            int lim = N - jb; if (lim > 32) lim = 32;
            for (int src = 0; src < lim; src++) {
                int j = jb + src;
                float v0 = Vs[j * 64 + lane];
                float v1 = Vs[j * 64 + lane + 32];
                #pragma unroll
                for (int qi = 0; qi < 8; qi++) {
                    float p = __shfl_sync(0xFFFFFFFFu, s[qi][jj], src);
                    a0[qi] += p * v0;
                    a1[qi] += p * v1;
                }
            }
        }
        #pragma unroll
        for (int qi = 0; qi < 8; qi++) {
            int q = qt + qi;
            if (q < N) {
                size_t oo = ((size_t)(b * N + q)) * Dm;
                int c0 = hd * 64 + lane;
                if (TF) {
                    Of[oo + permk(c0)]      = to_tf32(a0[qi] * inv[qi]);
                    Of[oo + permk(c0 + 32)] = to_tf32(a1[qi] * inv[qi]);
                } else {
                    split_store(Oh + oo + c0,      Ol + oo + c0,      a0[qi] * inv[qi]);
                    split_store(Oh + oo + c0 + 32, Ol + oo + c0 + 32, a1[qi] * inv[qi]);
                }
            }
        }
        __syncwarp();
    }
}

// ---------------- token selector ----------------
__global__ void selector_kernel(const float* __restrict__ X, const float* __restrict__ g,
                                const float* __restrict__ bt, const float* __restrict__ w1,
                                const float* __restrict__ b1, const float* __restrict__ w2,
                                const float* __restrict__ b2, float* __restrict__ scores) {
    __shared__ float hsm[768];
    __shared__ float red[4];
    __shared__ float stat[2];
    int t = blockIdx.x, tid = threadIdx.x;
    const float* xr = X + (size_t)t * Dm;
    float v[6];
    #pragma unroll
    for (int i = 0; i < 6; i++) v[i] = xr[tid + i * 128];
    float s = 0.f;
    #pragma unroll
    for (int i = 0; i < 6; i++) s += v[i];
    s = warp_sum(s);
    if ((tid & 31) == 0) red[tid >> 5] = s;
    __syncthreads();
    if (tid == 0) stat[0] = (red[0] + red[1] + red[2] + red[3]) * (1.f / 768.f);
    __syncthreads();
    float m = stat[0], q = 0.f;
    #pragma unroll
    for (int i = 0; i < 6; i++) { float d = v[i] - m; q += d * d; }
    q = warp_sum(q);
    if ((tid & 31) == 0) red[tid >> 5] = q;
    __syncthreads();
    if (tid == 0) stat[1] = rsqrtf((red[0] + red[1] + red[2] + red[3]) * (1.f / 768.f) + 1e-6f);
    __syncthreads();
    float rs = stat[1];
    #pragma unroll
    for (int i = 0; i < 6; i++)
        hsm[tid + i * 128] = (v[i] - m) * rs * g[tid + i * 128] + bt[tid + i * 128];
    __syncthreads();
    float acc = b1[tid];
    for (int k = 0; k < 768; k++) acc += hsm[k] * w1[k * 128 + tid];
    float gl = gelu_exact(acc) * w2[tid];
    gl = warp_sum(gl);
    if ((tid & 31) == 0) red[tid >> 5] = gl;
    __syncthreads();
    if (tid == 0) scores[t] = red[0] + red[1] + red[2] + red[3] + b2[0];
}

// ---------------- top-64 per batch ----------------
__global__ void topk_kernel(const float* __restrict__ scores, int* __restrict__ idx) {
    __shared__ float sv[196];
    __shared__ float rv[256];
    __shared__ int ri[256];
    int b = blockIdx.x, tid = threadIdx.x;
    if (tid < 196) sv[tid] = scores[b * NTOK + 1 + tid];
    if (tid == 0) idx[b * NSEL] = 0;
    __syncthreads();
    for (int it = 0; it < Kk; it++) {
        rv[tid] = (tid < 196) ? sv[tid] : -3e38f;
        ri[tid] = tid;
        __syncthreads();
        for (int s2 = 128; s2 > 0; s2 >>= 1) {
            if (tid < s2) {
                if (rv[tid + s2] > rv[tid] ||
                    (rv[tid + s2] == rv[tid] && ri[tid + s2] < ri[tid])) {
                    rv[tid] = rv[tid + s2];
                    ri[tid] = ri[tid + s2];
                }
            }
            __syncthreads();
        }
        if (tid == 0) { idx[b * NSEL + 1 + it] = ri[0] + 1; sv[ri[0]] = -3e38f; }
        __syncthreads();
    }
}

__global__ void gather_kernel(const float* __restrict__ X, const int* __restrict__ idx,
                              float* __restrict__ Xr) {
    int t = blockIdx.x;
    int b = t / NSEL;
    int src = idx[t];
    const float* s = X + ((size_t)b * NTOK + src) * Dm;
    float* d = Xr + (size_t)t * Dm;
    for (int i = threadIdx.x; i < Dm; i += 256) d[i] = s[i];
}

// ---------------- final LN(CLS) + head ----------------
__global__ void head_kernel(const float* __restrict__ Xr, const float* __restrict__ g,
                            const float* __restrict__ bt, const float* __restrict__ hw,
                            const float* __restrict__ hb, float* __restrict__ out) {
    __shared__ float hsm[768];
    __shared__ float red[8];
    __shared__ float stat[2];
    int b = blockIdx.x, tid = threadIdx.x;
    const float* xr = Xr + (size_t)b * NSEL * Dm;
    float v0 = xr[tid], v1 = xr[tid + 256], v2 = xr[tid + 512];
    float s = warp_sum(v0 + v1 + v2);
    if ((tid & 31) == 0) red[tid >> 5] = s;
    __syncthreads();
    if (tid < 8) {
        float r = red[tid];
        #pragma unroll
        for (int o = 4; o; o >>= 1) r += __shfl_xor_sync(0xFFu, r, o);
        if (tid == 0) stat[0] = r * (1.f / 768.f);
    }
    __syncthreads();
    float m = stat[0];
    float d0 = v0 - m, d1 = v1 - m, d2 = v2 - m;
    float q = warp_sum(d0 * d0 + d1 * d1 + d2 * d2);
    if ((tid & 31) == 0) red[tid >> 5] = q;
    __syncthreads();
    if (tid < 8) {
        float r = red[tid];
        #pragma unroll
        for (int o = 4; o; o >>= 1) r += __shfl_xor_sync(0xFFu, r, o);
        if (tid == 0) stat[1] = rsqrtf(r * (1.f / 768.f) + 1e-6f);
    }
    __syncthreads();
    float rs = stat[1];
    hsm[tid]       = d0 * rs * g[tid]       + bt[tid];
    hsm[tid + 256] = d1 * rs * g[tid + 256] + bt[tid + 256];
    hsm[tid + 512] = d2 * rs * g[tid + 512] + bt[tid + 512];
    __syncthreads();
    for (int c = 0; c < 10; c++) {
        float a = 0.f;
        for (int k = tid; k < 768; k += 256) a += hsm[k] * hw[k * 10 + c];
        a = warp_sum(a);
        if ((tid & 31) == 0) red[tid >> 5] = a;
        __syncthreads();
        if (tid == 0) {
            float r = 0.f;
            #pragma unroll
            for (int i = 0; i < 8; i++) r += red[i];
            out[b * 10 + c] = r + hb[c];
        }
        __syncthreads();
    }
}

// ---------------- host orchestration ----------------
extern "C" void kernel_launch(void* const* d_in, const int* in_sizes, int n_in,
                              void* d_out, int out_size) {
    const float* x        = (const float*)d_in[0];
    const float* patch_w  = (const float*)d_in[1];
    const float* patch_b  = (const float*)d_in[2];
    const float* cls_tok  = (const float*)d_in[3];
    const float* pos_emb  = (const float*)d_in[4];
    const float* ln1_g    = (const float*)d_in[5];
    const float* ln1_b    = (const float*)d_in[6];
    const float* qkv_w    = (const float*)d_in[7];
    const float* qkv_b    = (const float*)d_in[8];
    const float* proj_w   = (const float*)d_in[9];
    const float* proj_b   = (const float*)d_in[10];
    const float* ln2_g    = (const float*)d_in[11];
    const float* ln2_b    = (const float*)d_in[12];
    const float* fc1_w    = (const float*)d_in[13];
    const float* fc1_b    = (const float*)d_in[14];
    const float* fc2_w    = (const float*)d_in[15];
    const float* fc2_b    = (const float*)d_in[16];
    const float* sel_ln_g = (const float*)d_in[17];
    const float* sel_ln_b = (const float*)d_in[18];
    const float* sel_w1   = (const float*)d_in[19];
    const float* sel_b1   = (const float*)d_in[20];
    const float* sel_w2   = (const float*)d_in[21];
    const float* sel_b2   = (const float*)d_in[22];
    const float* norm_g   = (const float*)d_in[23];
    const float* norm_b   = (const float*)d_in[24];
    const float* head_w   = (const float*)d_in[25];
    const float* head_b   = (const float*)d_in[26];
    float* out = (float*)d_out;

    float *pX, *pH, *pQKV, *pScores, *pXr, *pF1f;
    float *pW32q, *pW32p, *pW32f1, *pW32f2;
    int* pIdx;
    __nv_bfloat16 *pAh, *pAl, *pF1h, *pF1l;
    __nv_bfloat16 *pWqkvh, *pWqkvl, *pWprojh, *pWprojl, *pW1h, *pW1l, *pW2h, *pW2l, *pPWh, *pPWl;
    cudaGetSymbolAddress((void**)&pX, g_X);
    cudaGetSymbolAddress((void**)&pH, g_Hbuf);
    cudaGetSymbolAddress((void**)&pQKV, g_QKV);
    cudaGetSymbolAddress((void**)&pScores, g_scores);
    cudaGetSymbolAddress((void**)&pIdx, g_idx);
    cudaGetSymbolAddress((void**)&pXr, g_Xr);
    cudaGetSymbolAddress((void**)&pF1f, g_F1f);
    cudaGetSymbolAddress((void**)&pAh, g_Ah);
    cudaGetSymbolAddress((void**)&pAl, g_Al);
    cudaGetSymbolAddress((void**)&pF1h, g_F1h);
    cudaGetSymbolAddress((void**)&pF1l, g_F1l);
    cudaGetSymbolAddress((void**)&pWqkvh, g_Wqkvh);
    cudaGetSymbolAddress((void**)&pWqkvl, g_Wqkvl);
    cudaGetSymbolAddress((void**)&pWprojh, g_Wprojh);
    cudaGetSymbolAddress((void**)&pWprojl, g_Wprojl);
    cudaGetSymbolAddress((void**)&pW1h, g_W1h);
    cudaGetSymbolAddress((void**)&pW1l, g_W1l);
    cudaGetSymbolAddress((void**)&pW2h, g_W2h);
    cudaGetSymbolAddress((void**)&pW2l, g_W2l);
    cudaGetSymbolAddress((void**)&pPWh, g_PWh);
    cudaGetSymbolAddress((void**)&pPWl, g_PWl);
    cudaGetSymbolAddress((void**)&pW32q, g_W32q);
    cudaGetSymbolAddress((void**)&pW32p, g_W32p);
    cudaGetSymbolAddress((void**)&pW32f1, g_W32f1);
    cudaGetSymbolAddress((void**)&pW32f2, g_W32f2);

    const int GEMM_SMEM = 2 * STAGE64;   // 73728
    const int TF_SMEM   = 2 * STAGEF;    // 73728
    cudaFuncSetAttribute(bgemm_kernel<0>, cudaFuncAttributeMaxDynamicSharedMemorySize, GEMM_SMEM);
    cudaFuncSetAttribute(bgemm_kernel<1>, cudaFuncAttributeMaxDynamicSharedMemorySize, GEMM_SMEM);
    cudaFuncSetAttribute(bgemm_kernel<2>, cudaFuncAttributeMaxDynamicSharedMemorySize, GEMM_SMEM);
    cudaFuncSetAttribute(tfgemm_kernel<0>, cudaFuncAttributeMaxDynamicSharedMemorySize, TF_SMEM);
    cudaFuncSetAttribute(tfgemm_kernel<1>, cudaFuncAttributeMaxDynamicSharedMemorySize, TF_SMEM);
    cudaFuncSetAttribute(tfgemm_kernel<2>, cudaFuncAttributeMaxDynamicSharedMemorySize, TF_SMEM);
    cudaFuncSetAttribute((const void*)attn_kernel<7, 0>,
                         cudaFuncAttributeMaxDynamicSharedMemorySize, 132 * 1024);
    cudaFuncSetAttribute((const void*)attn_kernel<3, 1>,
                         cudaFuncAttributeMaxDynamicSharedMemorySize, 132 * 1024);

    // weight conversion: warm -> bf16 hi/lo; refined -> tf32 transposed (K-permuted)
    dim3 ct(32, 8);
    convtrans_kernel<<<dim3(2304 / 32, 768 / 32, WARM), ct>>>(qkv_w, pWqkvh, pWqkvl, 768, 2304);
    convtrans_kernel<<<dim3(768 / 32, 768 / 32, WARM), ct>>>(proj_w, pWprojh, pWprojl, 768, 768);
    convtrans_kernel<<<dim3(3072 / 32, 768 / 32, WARM), ct>>>(fc1_w, pW1h, pW1l, 768, 3072);
    convtrans_kernel<<<dim3(768 / 32, 3072 / 32, WARM), ct>>>(fc2_w, pW2h, pW2l, 3072, 768);
    conv_patchw_kernel<<<(768 * 768 / 2 + 255) / 256, 256>>>(patch_w, pPWh, pPWl);
    convtrans_tf32_kernel<<<dim3(2304 / 32, 768 / 32, NREF), ct>>>(
        qkv_w + (size_t)WARM * 768 * 2304, pW32q, 768, 2304);
    convtrans_tf32_kernel<<<dim3(768 / 32, 768 / 32, NREF), ct>>>(
        proj_w + (size_t)WARM * 768 * 768, pW32p, 768, 768);
    convtrans_tf32_kernel<<<dim3(3072 / 32, 768 / 32, NREF), ct>>>(
        fc1_w + (size_t)WARM * 768 * 3072, pW32f1, 768, 3072);
    convtrans_tf32_kernel<<<dim3(768 / 32, 3072 / 32, NREF), ct>>>(
        fc2_w + (size_t)WARM * 3072 * 768, pW32f2, 3072, 768);

    // patch embed (bf16-3)
    im2col_kernel<<<Bb * 196, 256>>>(x, pAh, pAl);
    {
        dim3 grid(768 / 64, (Bb * 196 + 63) / 64);
        bgemm_kernel<0><<<grid, 128, GEMM_SMEM>>>(pAh, pAl, pPWh, pPWl, patch_b, nullptr,
                                                  pH, nullptr, nullptr, Bb * 196, 768, 768);
    }
    assemble_kernel<<<Bb * NTOK, 256>>>(pH, cls_tok, pos_emb, pX);

    for (int i = 0; i < DEPTH; i++) {
        const int N = (i < WARM) ? NTOK : NSEL;
        float* Xc = (i < WARM) ? pX : pXr;
        const int M = Bb * N;
        const int gy = (M + 63) / 64;
        dim3 gQKV(2304 / 64, gy), gD(768 / 64, gy), gMLP(3072 / 64, gy);
        size_t smem = ((size_t)N * 68 + (size_t)N * 64 + 8 * 512) * sizeof(float);

        if (i < WARM) {
            ln_kernel<0><<<M, 256>>>(Xc, ln1_g + (size_t)i * Dm, ln1_b + (size_t)i * Dm,
                                     pAh, pAl, nullptr);
            bgemm_kernel<0><<<gQKV, 128, GEMM_SMEM>>>(pAh, pAl,
                pWqkvh + (size_t)i * 2304 * 768, pWqkvl + (size_t)i * 2304 * 768,
                qkv_b + (size_t)i * 2304, nullptr, pQKV, nullptr, nullptr, M, 2304, 768);
            attn_kernel<7, 0><<<Bb * Hh, 256, smem>>>(pQKV, pAh, pAl, nullptr, N);
            bgemm_kernel<1><<<gD, 128, GEMM_SMEM>>>(pAh, pAl,
                pWprojh + (size_t)i * 768 * 768, pWprojl + (size_t)i * 768 * 768,
                proj_b + (size_t)i * 768, Xc, Xc, nullptr, nullptr, M, 768, 768);
            ln_kernel<0><<<M, 256>>>(Xc, ln2_g + (size_t)i * Dm, ln2_b + (size_t)i * Dm,
                                     pAh, pAl, nullptr);
            bgemm_kernel<2><<<gMLP, 128, GEMM_SMEM>>>(pAh, pAl,
                pW1h + (size_t)i * 3072 * 768, pW1l + (size_t)i * 3072 * 768,
                fc1_b + (size_t)i * 3072, nullptr, nullptr, pF1h, pF1l, M, 3072, 768);
            bgemm_kernel<1><<<gD, 128, GEMM_SMEM>>>(pF1h, pF1l,
                pW2h + (size_t)i * 768 * 3072, pW2l + (size_t)i * 768 * 3072,
                fc2_b + (size_t)i * 768, Xc, Xc, nullptr, nullptr, M, 768, 3072);
        } else {
            const int ri = i - WARM;
            ln_kernel<1><<<M, 256>>>(Xc, ln1_g + (size_t)i * Dm, ln1_b + (size_t)i * Dm,
                                     nullptr, nullptr, pH);
            tfgemm_kernel<0><<<gQKV, 128, TF_SMEM>>>(pH, pW32q + (size_t)ri * 2304 * 768,
                qkv_b + (size_t)i * 2304, nullptr, pQKV, M, 2304, 768);
            attn_kernel<3, 1><<<Bb * Hh, 256, smem>>>(pQKV, nullptr, nullptr, pH, N);
            tfgemm_kernel<1><<<gD, 128, TF_SMEM>>>(pH, pW32p + (size_t)ri * 768 * 768,
                proj_b + (size_t)i * 768, Xc, Xc, M, 768, 768);
            ln_kernel<1><<<M, 256>>>(Xc, ln2_g + (size_t)i * Dm, ln2_b + (size_t)i * Dm,
                                     nullptr, nullptr, pH);
            tfgemm_kernel<2><<<gMLP, 128, TF_SMEM>>>(pH, pW32f1 + (size_t)ri * 3072 * 768,
                fc1_b + (size_t)i * 3072, nullptr, pF1f, M, 3072, 768);
            tfgemm_kernel<1><<<gD, 128, TF_SMEM>>>(pF1f, pW32f2 + (size_t)ri * 768 * 3072,
                fc2_b + (size_t)i * 768, Xc, Xc, M, 768, 3072);
        }

        if (i == WARM - 1) {
            selector_kernel<<<Bb * NTOK, 128>>>(pX, sel_ln_g, sel_ln_b, sel_w1, sel_b1,
                                                sel_w2, sel_b2, pScores);
            topk_kernel<<<Bb, 256>>>(pScores, pIdx);
            gather_kernel<<<Bb * NSEL, 256>>>(pX, pIdx, pXr);
        }
    }

    head_kernel<<<Bb, 256>>>(pXr, norm_g, norm_b, head_w, head_b, out);
}

// round 16
// speedup vs baseline: 1.0372x; 1.0372x over previous
#include <cuda_runtime.h>
#include <cuda_bf16.h>
#include <math.h>

#define Dm 768
#define Hh 12
#define DEPTH 12
#define WARM 2
#define Kk 64
#define MLPD 3072
#define NTOK 197
#define NSEL 65
#define Bb 32
#define NREF (DEPTH - WARM)

// ---------------- scratch (device globals; no allocation) ----------------
__device__ __align__(16) float g_X[Bb * NTOK * Dm];
__device__ __align__(16) float g_Hbuf[Bb * NTOK * Dm];      // patch out / refined tf32 act
__device__ __align__(16) float g_QKV[Bb * NTOK * 3 * Dm];
__device__ float g_scores[Bb * NTOK];
__device__ int   g_idx[Bb * NSEL];
__device__ __align__(16) float g_Xr[Bb * NSEL * Dm];
__device__ __align__(16) float g_F1f[Bb * NSEL * MLPD];     // refined fc1 out (tf32, K-permuted)

__device__ __align__(16) __nv_bfloat16 g_Ah[Bb * NTOK * Dm];
__device__ __align__(16) __nv_bfloat16 g_Al[Bb * NTOK * Dm];
__device__ __align__(16) __nv_bfloat16 g_F1h[Bb * NTOK * MLPD];
__device__ __align__(16) __nv_bfloat16 g_F1l[Bb * NTOK * MLPD];

__device__ __align__(16) __nv_bfloat16 g_Wqkvh[WARM * 2304 * 768];
__device__ __align__(16) __nv_bfloat16 g_Wqkvl[WARM * 2304 * 768];
__device__ __align__(16) __nv_bfloat16 g_Wprojh[WARM * 768 * 768];
__device__ __align__(16) __nv_bfloat16 g_Wprojl[WARM * 768 * 768];
__device__ __align__(16) __nv_bfloat16 g_W1h[WARM * 3072 * 768];
__device__ __align__(16) __nv_bfloat16 g_W1l[WARM * 3072 * 768];
__device__ __align__(16) __nv_bfloat16 g_W2h[WARM * 768 * 3072];
__device__ __align__(16) __nv_bfloat16 g_W2l[WARM * 768 * 3072];
__device__ __align__(16) __nv_bfloat16 g_PWh[768 * 768];
__device__ __align__(16) __nv_bfloat16 g_PWl[768 * 768];

// refined tf32 weights (transposed [N,K], f32 containers, tf32-rounded, K-permuted)
__device__ __align__(16) float g_W32q[NREF * 2304 * 768];
__device__ __align__(16) float g_W32p[NREF * 768 * 768];
__device__ __align__(16) float g_W32f1[NREF * 3072 * 768];
__device__ __align__(16) float g_W32f2[NREF * 768 * 3072];

// ---------------- helpers ----------------
__device__ __forceinline__ float gelu_exact(float x) {
    return 0.5f * x * (1.0f + erff(x * 0.70710678118654752440f));
}
__device__ __forceinline__ float warp_sum(float v) {
    #pragma unroll
    for (int o = 16; o; o >>= 1) v += __shfl_xor_sync(0xFFFFFFFFu, v, o);
    return v;
}
__device__ __forceinline__ float warp_max(float v) {
    #pragma unroll
    for (int o = 16; o; o >>= 1) v = fmaxf(v, __shfl_xor_sync(0xFFFFFFFFu, v, o));
    return v;
}
__device__ __forceinline__ void split_store(__nv_bfloat16* ph, __nv_bfloat16* pl, float v) {
    __nv_bfloat16 hv = __float2bfloat16(v);
    *ph = hv;
    *pl = __float2bfloat16(v - __bfloat162float(hv));
}
__device__ __forceinline__ float to_tf32(float x) {
    unsigned u;
    asm("cvt.rna.tf32.f32 %0, %1;" : "=r"(u) : "f"(x));
    return __uint_as_float(u);
}
// K-label permutation within 8-groups: order [0,4,1,5,2,6,3,7]
__device__ __forceinline__ int permk(int k) {
    return (k & ~7) | (((k & 3) << 1) | ((k >> 2) & 1));
}
__device__ __forceinline__ unsigned smem_u32(const void* p) {
    unsigned a;
    asm("{ .reg .u64 t; cvta.to.shared.u64 t, %1; cvt.u32.u64 %0, t; }" : "=r"(a) : "l"(p));
    return a;
}
__device__ __forceinline__ void cp16(unsigned dst, const void* src, bool pred) {
    int sz = pred ? 16 : 0;
    asm volatile("cp.async.cg.shared.global [%0], [%1], 16, %2;\n"
                 :: "r"(dst), "l"(src), "r"(sz));
}
__device__ __forceinline__ void cp_commit() {
    asm volatile("cp.async.commit_group;\n" ::);
}
template<int NG>
__device__ __forceinline__ void cp_wait() {
    asm volatile("cp.async.wait_group %0;\n" :: "n"(NG));
}
__device__ __forceinline__ void ldsm4(unsigned* r, unsigned a) {
    asm volatile("ldmatrix.sync.aligned.m8n8.x4.shared.b16 {%0,%1,%2,%3}, [%4];\n"
                 : "=r"(r[0]), "=r"(r[1]), "=r"(r[2]), "=r"(r[3]) : "r"(a));
}
__device__ __forceinline__ void mma16816(float* c, const unsigned* a, const unsigned* b) {
    asm volatile(
        "mma.sync.aligned.m16n8k16.row.col.f32.bf16.bf16.f32 "
        "{%0,%1,%2,%3}, {%4,%5,%6,%7}, {%8,%9}, {%0,%1,%2,%3};\n"
        : "+f"(c[0]), "+f"(c[1]), "+f"(c[2]), "+f"(c[3])
        : "r"(a[0]), "r"(a[1]), "r"(a[2]), "r"(a[3]), "r"(b[0]), "r"(b[1]));
}
__device__ __forceinline__ void mma16808tf(float* c, const unsigned* a, const unsigned* b) {
    asm volatile(
        "mma.sync.aligned.m16n8k8.row.col.f32.tf32.tf32.f32 "
        "{%0,%1,%2,%3}, {%4,%5,%6,%7}, {%8,%9}, {%0,%1,%2,%3};\n"
        : "+f"(c[0]), "+f"(c[1]), "+f"(c[2]), "+f"(c[3])
        : "r"(a[0]), "r"(a[1]), "r"(a[2]), "r"(a[3]), "r"(b[0]), "r"(b[1]));
}

// ================= split-bf16 mma.sync GEMM, 64x64 tiles (warm + patch) =========
#define LDT 72
#define TILE64 (64 * LDT * 2)
#define STAGE64 (4 * TILE64)

__device__ __forceinline__ void load_stage(unsigned sbuf,
                                           const __nv_bfloat16* __restrict__ Sa_h,
                                           const __nv_bfloat16* __restrict__ Sa_l,
                                           const __nv_bfloat16* __restrict__ Sb_h,
                                           const __nv_bfloat16* __restrict__ Sb_l,
                                           int rowA, int Mlim, int rowB, int Nlim,
                                           int ldK, int k0, int tid) {
    const int ch = tid & 7, rr = tid >> 3;
    #pragma unroll
    for (int j = 0; j < 4; j++) {
        int r = j * 16 + rr;
        unsigned doff = (unsigned)(r * (LDT * 2) + ch * 16);
        {
            int gr = rowA + r;
            bool ok = gr < Mlim;
            int cr = ok ? gr : (Mlim - 1);
            size_t so = (size_t)cr * ldK + k0 + ch * 8;
            cp16(sbuf + doff, Sa_h + so, ok);
            cp16(sbuf + TILE64 + doff, Sa_l + so, ok);
        }
        {
            int gb = rowB + r;
            bool ok = gb < Nlim;
            int cb = ok ? gb : (Nlim - 1);
            size_t so = (size_t)cb * ldK + k0 + ch * 8;
            cp16(sbuf + 2 * TILE64 + doff, Sb_h + so, ok);
            cp16(sbuf + 3 * TILE64 + doff, Sb_l + so, ok);
        }
    }
}

template<int EPI>   // 0 bias; 1 bias+res; 2 bias+GELU->bf16 pair
__global__ void __launch_bounds__(128, 3)
bgemm_kernel(const __nv_bfloat16* __restrict__ Ah, const __nv_bfloat16* __restrict__ Al,
             const __nv_bfloat16* __restrict__ Bh, const __nv_bfloat16* __restrict__ Bl,
             const float* __restrict__ bias, const float* __restrict__ Cin,
             float* __restrict__ outF, __nv_bfloat16* __restrict__ outBh,
             __nv_bfloat16* __restrict__ outBl, int M, int N, int K) {
    extern __shared__ char smv[];
    const int tid = threadIdx.x;
    const int wid = tid >> 5, lane = tid & 31;
    const int blockRow = blockIdx.y << 6;
    const int blockCol = blockIdx.x << 6;
    const int wm = (wid >> 1) << 5;
    const int wn = (wid & 1) << 5;
    const unsigned sb = smem_u32(smv);

    float acc[2][4][4];
    #pragma unroll
    for (int i = 0; i < 2; i++)
        #pragma unroll
        for (int j = 0; j < 4; j++) {
            acc[i][j][0] = 0.f; acc[i][j][1] = 0.f; acc[i][j][2] = 0.f; acc[i][j][3] = 0.f;
        }

    const int T = K >> 6;
    load_stage(sb, Ah, Al, Bh, Bl, blockRow, M, blockCol, N, K, 0, tid);
    cp_commit();

    const int arow = (lane & 15);
    const int kofA = (lane >> 4) << 3;
    const int brow = ((lane >> 4) << 3) + (lane & 7);
    const int kofB = lane & 8;

    for (int kt = 0; kt < T; kt++) {
        if (kt + 1 < T) {
            load_stage(sb + (unsigned)((kt + 1) & 1) * STAGE64, Ah, Al, Bh, Bl,
                       blockRow, M, blockCol, N, K, (kt + 1) << 6, tid);
            cp_commit();
            cp_wait<1>();
        } else {
            cp_wait<0>();
        }
        __syncthreads();

        const unsigned bufb = sb + (unsigned)(kt & 1) * STAGE64;
        const unsigned aB = bufb + (unsigned)((wm + arow) * (LDT * 2));
        const unsigned bB = bufb + 2 * TILE64 + (unsigned)((wn + brow) * (LDT * 2));
        #pragma unroll
        for (int ks = 0; ks < 4; ks++) {
            const int kk = ks << 4;
            unsigned ah[2][4], al[2][4], bh[4][2], bl[4][2];
            #pragma unroll
            for (int mi = 0; mi < 2; mi++) {
                unsigned ad = aB + (unsigned)(mi * 16 * (LDT * 2) + (kk + kofA) * 2);
                ldsm4(ah[mi], ad);
                ldsm4(al[mi], ad + TILE64);
            }
            #pragma unroll
            for (int nj = 0; nj < 2; nj++) {
                unsigned bd = bB + (unsigned)(nj * 16 * (LDT * 2) + (kk + kofB) * 2);
                unsigned t0[4], t1[4];
                ldsm4(t0, bd);
                ldsm4(t1, bd + TILE64);
                bh[nj * 2][0] = t0[0]; bh[nj * 2][1] = t0[1];
                bh[nj * 2 + 1][0] = t0[2]; bh[nj * 2 + 1][1] = t0[3];
                bl[nj * 2][0] = t1[0]; bl[nj * 2][1] = t1[1];
                bl[nj * 2 + 1][0] = t1[2]; bl[nj * 2 + 1][1] = t1[3];
            }
            #pragma unroll
            for (int mi = 0; mi < 2; mi++)
                #pragma unroll
                for (int ni = 0; ni < 4; ni++) {
                    mma16816(acc[mi][ni], ah[mi], bh[ni]);
                    mma16816(acc[mi][ni], ah[mi], bl[ni]);
                    mma16816(acc[mi][ni], al[mi], bh[ni]);
                }
        }
        __syncthreads();
    }

    const int gid = lane >> 2, tig = lane & 3;
    #pragma unroll
    for (int mi = 0; mi < 2; mi++) {
        #pragma unroll
        for (int ni = 0; ni < 4; ni++) {
            const int gr0 = blockRow + wm + mi * 16 + gid;
            const int gc = blockCol + wn + ni * 8 + tig * 2;
            const float b0v = bias[gc], b1v = bias[gc + 1];
            #pragma unroll
            for (int hf = 0; hf < 2; hf++) {
                const int gr = gr0 + hf * 8;
                if (gr < M) {
                    float v0 = acc[mi][ni][hf * 2 + 0] + b0v;
                    float v1 = acc[mi][ni][hf * 2 + 1] + b1v;
                    if (EPI == 1) {
                        const float2 rv = *(const float2*)(Cin + (size_t)gr * N + gc);
                        v0 += rv.x; v1 += rv.y;
                    }
                    if (EPI == 2) {
                        v0 = gelu_exact(v0); v1 = gelu_exact(v1);
                        __nv_bfloat16 h0 = __float2bfloat16(v0);
                        __nv_bfloat16 h1 = __float2bfloat16(v1);
                        __nv_bfloat162 hp; hp.x = h0; hp.y = h1;
                        __nv_bfloat162 lp;
                        lp.x = __float2bfloat16(v0 - __bfloat162float(h0));
                        lp.y = __float2bfloat16(v1 - __bfloat162float(h1));
                        *(__nv_bfloat162*)(outBh + (size_t)gr * N + gc) = hp;
                        *(__nv_bfloat162*)(outBl + (size_t)gr * N + gc) = lp;
                    } else {
                        float2 o; o.x = v0; o.y = v1;
                        *(float2*)(outF + (size_t)gr * N + gc) = o;
                    }
                }
            }
        }
    }
}

// ================= single-MMA tf32 GEMM, 64x64 tiles, permuted-K float2 loads =========
#define LDF 72
#define TILEF (64 * LDF * 4)       // 18432 B
#define STAGEF (2 * TILEF)         // 36864 B

__device__ __forceinline__ void load_stage_f(unsigned sbuf,
                                             const float* __restrict__ Af,
                                             const float* __restrict__ Bf,
                                             int rowA, int Mlim, int rowB, int Nlim,
                                             int ldK, int k0, int tid) {
    #pragma unroll
    for (int i = 0; i < 8; i++) {
        int idx = tid + i * 128;
        int r = idx >> 4, ch = idx & 15;
        unsigned doff = (unsigned)(r * (LDF * 4) + ch * 16);
        {
            int gr = rowA + r;
            bool ok = gr < Mlim;
            int cr = ok ? gr : (Mlim - 1);
            cp16(sbuf + doff, Af + (size_t)cr * ldK + k0 + ch * 4, ok);
        }
        {
            int gb = rowB + r;
            bool ok = gb < Nlim;
            int cb = ok ? gb : (Nlim - 1);
            cp16(sbuf + TILEF + doff, Bf + (size_t)cb * ldK + k0 + ch * 4, ok);
        }
    }
}

template<int EPI>   // 0 bias->f32; 1 bias+res->f32; 2 bias+GELU->tf32 f32 (K-permuted out)
__global__ void __launch_bounds__(128, 3)
tfgemm_kernel(const float* __restrict__ A, const float* __restrict__ B,
              const float* __restrict__ bias, const float* __restrict__ Cin,
              float* __restrict__ outF, int M, int N, int K) {
    extern __shared__ char smv[];
    const int tid = threadIdx.x;
    const int wid = tid >> 5, lane = tid & 31;
    const int blockRow = blockIdx.y << 6;
    const int blockCol = blockIdx.x << 6;
    const int wm = (wid >> 1) << 5;
    const int wn = (wid & 1) << 5;
    const unsigned sb = smem_u32(smv);
    const float2* sm2 = (const float2*)smv;

    float acc[2][4][4];
    #pragma unroll
    for (int i = 0; i < 2; i++)
        #pragma unroll
        for (int j = 0; j < 4; j++) {
            acc[i][j][0] = 0.f; acc[i][j][1] = 0.f; acc[i][j][2] = 0.f; acc[i][j][3] = 0.f;
        }

    const int T = K >> 6;
    load_stage_f(sb, A, B, blockRow, M, blockCol, N, K, 0, tid);
    cp_commit();

    const int gid = lane >> 2, tig = lane & 3;

    for (int kt = 0; kt < T; kt++) {
        if (kt + 1 < T) {
            load_stage_f(sb + (unsigned)((kt + 1) & 1) * STAGEF, A, B,
                         blockRow, M, blockCol, N, K, (kt + 1) << 6, tid);
            cp_commit();
            cp_wait<1>();
        } else {
            cp_wait<0>();
        }
        __syncthreads();

        // float2 units: stage offset, B-tile offset, row stride LDF/2 = 36
        const unsigned bufw2 = (unsigned)(kt & 1) * (STAGEF / 8);
        #pragma unroll
        for (int ks = 0; ks < 8; ks++) {
            const int kk2 = ks << 2;   // k/2
            unsigned af[2][4], bf[4][2];
            #pragma unroll
            for (int mi = 0; mi < 2; mi++) {
                unsigned r0 = bufw2 + (unsigned)((wm + mi * 16 + gid) * 36 + kk2 + tig);
                float2 alo = sm2[r0];             // rows gid   : (k+tig, k+tig+4)
                float2 ahi = sm2[r0 + 4 * LDF];   // rows gid+8
                af[mi][0] = __float_as_uint(alo.x);
                af[mi][2] = __float_as_uint(alo.y);
                af[mi][1] = __float_as_uint(ahi.x);
                af[mi][3] = __float_as_uint(ahi.y);
            }
            #pragma unroll
            for (int ni = 0; ni < 4; ni++) {
                unsigned rb = bufw2 + (unsigned)(TILEF / 8) +
                              (unsigned)((wn + ni * 8 + gid) * 36 + kk2 + tig);
                float2 bv = sm2[rb];
                bf[ni][0] = __float_as_uint(bv.x);
                bf[ni][1] = __float_as_uint(bv.y);
            }
            #pragma unroll
            for (int mi = 0; mi < 2; mi++)
                #pragma unroll
                for (int ni = 0; ni < 4; ni++)
                    mma16808tf(acc[mi][ni], af[mi], bf[ni]);
        }
        __syncthreads();
    }

    #pragma unroll
    for (int mi = 0; mi < 2; mi++) {
        #pragma unroll
        for (int ni = 0; ni < 4; ni++) {
            const int gr0 = blockRow + wm + mi * 16 + gid;
            const int gc = blockCol + wn + ni * 8 + tig * 2;
            const float b0v = bias[gc], b1v = bias[gc + 1];
            #pragma unroll
            for (int hf = 0; hf < 2; hf++) {
                const int gr = gr0 + hf * 8;
                if (gr < M) {
                    float v0 = acc[mi][ni][hf * 2 + 0] + b0v;
                    float v1 = acc[mi][ni][hf * 2 + 1] + b1v;
                    if (EPI == 1) {
                        const float2 rv = *(const float2*)(Cin + (size_t)gr * N + gc);
                        v0 += rv.x; v1 += rv.y;
                    }
                    if (EPI == 2) {
                        v0 = to_tf32(gelu_exact(v0));
                        v1 = to_tf32(gelu_exact(v1));
                        outF[(size_t)gr * N + permk(gc)]     = v0;
                        outF[(size_t)gr * N + permk(gc + 1)] = v1;
                    } else {
                        float2 o; o.x = v0; o.y = v1;
                        *(float2*)(outF + (size_t)gr * N + gc) = o;
                    }
                }
            }
        }
    }
}

// ---------------- weight converts ----------------
__global__ void convtrans_kernel(const float* __restrict__ W, __nv_bfloat16* __restrict__ Wh,
                                 __nv_bfloat16* __restrict__ Wl, int K, int N) {
    __shared__ float ts[32][33];
    const int l = blockIdx.z;
    const size_t off = (size_t)l * K * N;
    const int kb = blockIdx.y << 5, nb = blockIdx.x << 5;
    #pragma unroll
    for (int j = 0; j < 4; j++)
        ts[threadIdx.y + 8 * j][threadIdx.x] =
            W[off + (size_t)(kb + threadIdx.y + 8 * j) * N + nb + threadIdx.x];
    __syncthreads();
    const int tid = threadIdx.y * 32 + threadIdx.x;
    const int c2 = tid & 15, r0 = tid >> 4;
    #pragma unroll
    for (int j = 0; j < 2; j++) {
        int r = r0 + 16 * j;
        float v0 = ts[2 * c2][r], v1 = ts[2 * c2 + 1][r];
        __nv_bfloat16 h0 = __float2bfloat16(v0), h1 = __float2bfloat16(v1);
        __nv_bfloat162 hp; hp.x = h0; hp.y = h1;
        __nv_bfloat162 lp;
        lp.x = __float2bfloat16(v0 - __bfloat162float(h0));
        lp.y = __float2bfloat16(v1 - __bfloat162float(h1));
        size_t di = off + (size_t)(nb + r) * K + kb + 2 * c2;
        *(__nv_bfloat162*)(Wh + di) = hp;
        *(__nv_bfloat162*)(Wl + di) = lp;
    }
}

// tf32 transpose-convert with K-permutation
__global__ void convtrans_tf32_kernel(const float* __restrict__ W, float* __restrict__ Wt,
                                      int K, int N) {
    __shared__ float ts[32][33];
    const int l = blockIdx.z;
    const size_t off = (size_t)l * K * N;
    const int kb = blockIdx.y << 5, nb = blockIdx.x << 5;
    #pragma unroll
    for (int j = 0; j < 4; j++)
        ts[threadIdx.y + 8 * j][threadIdx.x] =
            W[off + (size_t)(kb + threadIdx.y + 8 * j) * N + nb + threadIdx.x];
    __syncthreads();
    const int tid = threadIdx.y * 32 + threadIdx.x;
    const int c2 = tid & 15, r0 = tid >> 4;
    #pragma unroll
    for (int j = 0; j < 2; j++) {
        int r = r0 + 16 * j;
        size_t rbase = off + (size_t)(nb + r) * K;
        Wt[rbase + permk(kb + 2 * c2)]     = to_tf32(ts[2 * c2][r]);
        Wt[rbase + permk(kb + 2 * c2 + 1)] = to_tf32(ts[2 * c2 + 1][r]);
    }
}

__global__ void conv_patchw_kernel(const float* __restrict__ W, __nv_bfloat16* __restrict__ Wh,
                                   __nv_bfloat16* __restrict__ Wl) {
    int i = blockIdx.x * 256 + threadIdx.x;
    if (i < 768 * 768 / 2) {
        float2 v = *(const float2*)(W + 2 * i);
        __nv_bfloat16 h0 = __float2bfloat16(v.x), h1 = __float2bfloat16(v.y);
        __nv_bfloat162 hp; hp.x = h0; hp.y = h1;
        __nv_bfloat162 lp;
        lp.x = __float2bfloat16(v.x - __bfloat162float(h0));
        lp.y = __float2bfloat16(v.y - __bfloat162float(h1));
        *(__nv_bfloat162*)(Wh + 2 * i) = hp;
        *(__nv_bfloat162*)(Wl + 2 * i) = lp;
    }
}

// ---------------- im2col / assemble ----------------
__global__ void im2col_kernel(const float* __restrict__ x, __nv_bfloat16* __restrict__ Ph,
                              __nv_bfloat16* __restrict__ Pl) {
    int t = blockIdx.x;
    int b = t / 196, p = t % 196;
    int py = p / 14, px = p % 14;
    for (int d = threadIdx.x; d < Dm; d += 256) {
        int c = d >> 8, r = (d >> 4) & 15, col = d & 15;
        float v = x[(((size_t)b * 3 + c) * 224 + py * 16 + r) * 224 + px * 16 + col];
        split_store(Ph + (size_t)t * Dm + d, Pl + (size_t)t * Dm + d, v);
    }
}

__global__ void assemble_kernel(const float* __restrict__ P, const float* __restrict__ cls,
                                const float* __restrict__ pos, float* __restrict__ X) {
    int t = blockIdx.x;
    int b = t / NTOK, n = t % NTOK;
    float* xr = X + (size_t)t * Dm;
    const float* pr = pos + (size_t)n * Dm;
    if (n == 0) {
        for (int d = threadIdx.x; d < Dm; d += 256) xr[d] = cls[d] + pr[d];
    } else {
        const float* pp = P + ((size_t)(b * 196 + n - 1)) * Dm;
        for (int d = threadIdx.x; d < Dm; d += 256) xr[d] = pp[d] + pr[d];
    }
}

// ---------------- LayerNorm variants ----------------
template<int TF>    // 0: bf16 hi/lo out ; 1: tf32 f32 out (K-permuted)
__global__ void ln_kernel(const float* __restrict__ X, const float* __restrict__ g,
                          const float* __restrict__ bt, __nv_bfloat16* __restrict__ Yh,
                          __nv_bfloat16* __restrict__ Yl, float* __restrict__ Yf) {
    __shared__ float red[8];
    __shared__ float stat[2];
    int t = blockIdx.x, tid = threadIdx.x;
    const float* xr = X + (size_t)t * Dm;
    float v0 = xr[tid], v1 = xr[tid + 256], v2 = xr[tid + 512];
    float s = warp_sum(v0 + v1 + v2);
    if ((tid & 31) == 0) red[tid >> 5] = s;
    __syncthreads();
    if (tid < 8) {
        float r = red[tid];
        #pragma unroll
        for (int o = 4; o; o >>= 1) r += __shfl_xor_sync(0xFFu, r, o);
        if (tid == 0) stat[0] = r * (1.f / 768.f);
    }
    __syncthreads();
    float m = stat[0];
    float d0 = v0 - m, d1 = v1 - m, d2 = v2 - m;
    float q = warp_sum(d0 * d0 + d1 * d1 + d2 * d2);
    if ((tid & 31) == 0) red[tid >> 5] = q;
    __syncthreads();
    if (tid < 8) {
        float r = red[tid];
        #pragma unroll
        for (int o = 4; o; o >>= 1) r += __shfl_xor_sync(0xFFu, r, o);
        if (tid == 0) stat[1] = rsqrtf(r * (1.f / 768.f) + 1e-6f);
    }
    __syncthreads();
    float rs = stat[1];
    size_t base = (size_t)t * Dm;
    float y0 = d0 * rs * g[tid]       + bt[tid];
    float y1 = d1 * rs * g[tid + 256] + bt[tid + 256];
    float y2 = d2 * rs * g[tid + 512] + bt[tid + 512];
    if (TF) {
        Yf[base + permk(tid)]       = to_tf32(y0);
        Yf[base + permk(tid + 256)] = to_tf32(y1);
        Yf[base + permk(tid + 512)] = to_tf32(y2);
    } else {
        split_store(Yh + base + tid,       Yl + base + tid,       y0);
        split_store(Yh + base + tid + 256, Yl + base + tid + 256, y1);
        split_store(Yh + base + tid + 512, Yl + base + tid + 512, y2);
    }
}

// ---------------- fused attention, 8 queries per warp ----------------
template<int NJ, int TF>
__global__ void __launch_bounds__(256)
attn_kernel(const float* __restrict__ QKV, __nv_bfloat16* __restrict__ Oh,
            __nv_bfloat16* __restrict__ Ol, float* __restrict__ Of, int N) {
    extern __shared__ float smf[];
    float* Ks = smf;
    float* Vs = Ks + N * 68;
    float* qs = Vs + N * 64;
    int b = blockIdx.x / Hh, hd = blockIdx.x % Hh;
    int tid = threadIdx.x, w = tid >> 5, lane = tid & 31;
    const float* base = QKV + (size_t)b * N * (3 * Dm);
    for (int idx = tid; idx < N * 64; idx += 256) {
        int n = idx >> 6, d = idx & 63;
        Ks[n * 68 + d] = base[(size_t)n * (3 * Dm) + Dm + hd * 64 + d];
        Vs[idx]        = base[(size_t)n * (3 * Dm) + 2 * Dm + hd * 64 + d];
    }
    __syncthreads();
    float* qw = qs + w * 512;
    for (int qt = w * 8; qt < N; qt += 64) {
        #pragma unroll
        for (int qi = 0; qi < 8; qi++) {
            int q = qt + qi;
            if (q < N) {
                const float* qp = base + (size_t)q * (3 * Dm) + hd * 64;
                qw[qi * 64 + lane]      = qp[lane]      * 0.125f;
                qw[qi * 64 + lane + 32] = qp[lane + 32] * 0.125f;
            }
        }
        __syncwarp();
        float s[8][NJ];
        #pragma unroll
        for (int qi = 0; qi < 8; qi++)
            #pragma unroll
            for (int jj = 0; jj < NJ; jj++) s[qi][jj] = -3e38f;
        #pragma unroll
        for (int jj = 0; jj < NJ; jj++) {
            int j = jj * 32 + lane;
            if (j < N) {
                const float4* k4 = (const float4*)(Ks + j * 68);
                float acc[8];
                #pragma unroll
                for (int qi = 0; qi < 8; qi++) acc[qi] = 0.f;
                #pragma unroll
                for (int d = 0; d < 16; d++) {
                    float4 kv = k4[d];
                    #pragma unroll
                    for (int qi = 0; qi < 8; qi++) {
                        float4 qv = ((const float4*)(qw + qi * 64))[d];
                        acc[qi] += qv.x * kv.x + qv.y * kv.y + qv.z * kv.z + qv.w * kv.w;
                    }
                }
                #pragma unroll
                for (int qi = 0; qi < 8; qi++) s[qi][jj] = acc[qi];
            }
        }
        float inv[8];
        #pragma unroll
        for (int qi = 0; qi < 8; qi++) {
            float m = -3e38f;
            #pragma unroll
            for (int jj = 0; jj < NJ; jj++) m = fmaxf(m, s[qi][jj]);
            m = warp_max(m);
            float sum = 0.f;
            #pragma unroll
            for (int jj = 0; jj < NJ; jj++) {
                float e = expf(s[qi][jj] - m);
                s[qi][jj] = e;
                sum += e;
            }
            sum = warp_sum(sum);
            inv[qi] = 1.f / sum;
        }
        float a0[8], a1[8];
        #pragma unroll
        for (int qi = 0; qi < 8; qi++) { a0[qi] = 0.f; a1[qi] = 0.f; }
        #pragma unroll
        for (int jj = 0; jj < NJ; jj++) {
            int jb = jj * 32;
            int lim = N - jb; if (lim > 32) lim = 32;
            for (int src = 0; src < lim; src++) {
                int j = jb + src;
                float v0 = Vs[j * 64 + lane];
                float v1 = Vs[j * 64 + lane + 32];
                #pragma unroll
                for (int qi = 0; qi < 8; qi++) {
                    float p = __shfl_sync(0xFFFFFFFFu, s[qi][jj], src);
                    a0[qi] += p * v0;
                    a1[qi] += p * v1;
                }
            }
        }
        #pragma unroll
        for (int qi = 0; qi < 8; qi++) {
            int q = qt + qi;
            if (q < N) {
                size_t oo = ((size_t)(b * N + q)) * Dm;
                int c0 = hd * 64 + lane;
                if (TF) {
                    Of[oo + permk(c0)]      = to_tf32(a0[qi] * inv[qi]);
                    Of[oo + permk(c0 + 32)] = to_tf32(a1[qi] * inv[qi]);
                } else {
                    split_store(Oh + oo + c0,      Ol + oo + c0,      a0[qi] * inv[qi]);
                    split_store(Oh + oo + c0 + 32, Ol + oo + c0 + 32, a1[qi] * inv[qi]);
                }
            }
        }
        __syncwarp();
    }
}

// ---------------- token selector ----------------
__global__ void selector_kernel(const float* __restrict__ X, const float* __restrict__ g,
                                const float* __restrict__ bt, const float* __restrict__ w1,
                                const float* __restrict__ b1, const float* __restrict__ w2,
                                const float* __restrict__ b2, float* __restrict__ scores) {
    __shared__ float hsm[768];
    __shared__ float red[4];
    __shared__ float stat[2];
    int t = blockIdx.x, tid = threadIdx.x;
    const float* xr = X + (size_t)t * Dm;
    float v[6];
    #pragma unroll
    for (int i = 0; i < 6; i++) v[i] = xr[tid + i * 128];
    float s = 0.f;
    #pragma unroll
    for (int i = 0; i < 6; i++) s += v[i];
    s = warp_sum(s);
    if ((tid & 31) == 0) red[tid >> 5] = s;
    __syncthreads();
    if (tid == 0) stat[0] = (red[0] + red[1] + red[2] + red[3]) * (1.f / 768.f);
    __syncthreads();
    float m = stat[0], q = 0.f;
    #pragma unroll
    for (int i = 0; i < 6; i++) { float d = v[i] - m; q += d * d; }
    q = warp_sum(q);
    if ((tid & 31) == 0) red[tid >> 5] = q;
    __syncthreads();
    if (tid == 0) stat[1] = rsqrtf((red[0] + red[1] + red[2] + red[3]) * (1.f / 768.f) + 1e-6f);
    __syncthreads();
    float rs = stat[1];
    #pragma unroll
    for (int i = 0; i < 6; i++)
        hsm[tid + i * 128] = (v[i] - m) * rs * g[tid + i * 128] + bt[tid + i * 128];
    __syncthreads();
    float acc = b1[tid];
    for (int k = 0; k < 768; k++) acc += hsm[k] * w1[k * 128 + tid];
    float gl = gelu_exact(acc) * w2[tid];
    gl = warp_sum(gl);
    if ((tid & 31) == 0) red[tid >> 5] = gl;
    __syncthreads();
    if (tid == 0) scores[t] = red[0] + red[1] + red[2] + red[3] + b2[0];
}

// ---------------- top-64 per batch ----------------
__global__ void topk_kernel(const float* __restrict__ scores, int* __restrict__ idx) {
    __shared__ float sv[196];
    __shared__ float rv[256];
    __shared__ int ri[256];
    int b = blockIdx.x, tid = threadIdx.x;
    if (tid < 196) sv[tid] = scores[b * NTOK + 1 + tid];
    if (tid == 0) idx[b * NSEL] = 0;
    __syncthreads();
    for (int it = 0; it < Kk; it++) {
        rv[tid] = (tid < 196) ? sv[tid] : -3e38f;
        ri[tid] = tid;
        __syncthreads();
        for (int s2 = 128; s2 > 0; s2 >>= 1) {
            if (tid < s2) {
                if (rv[tid + s2] > rv[tid] ||
                    (rv[tid + s2] == rv[tid] && ri[tid + s2] < ri[tid])) {
                    rv[tid] = rv[tid + s2];
                    ri[tid] = ri[tid + s2];
                }
            }
            __syncthreads();
        }
        if (tid == 0) { idx[b * NSEL + 1 + it] = ri[0] + 1; sv[ri[0]] = -3e38f; }
        __syncthreads();
    }
}

__global__ void gather_kernel(const float* __restrict__ X, const int* __restrict__ idx,
                              float* __restrict__ Xr) {
    int t = blockIdx.x;
    int b = t / NSEL;
    int src = idx[t];
    const float* s = X + ((size_t)b * NTOK + src) * Dm;
    float* d = Xr + (size_t)t * Dm;
    for (int i = threadIdx.x; i < Dm; i += 256) d[i] = s[i];
}

// ---------------- final LN(CLS) + head ----------------
__global__ void head_kernel(const float* __restrict__ Xr, const float* __restrict__ g,
                            const float* __restrict__ bt, const float* __restrict__ hw,
                            const float* __restrict__ hb, float* __restrict__ out) {
    __shared__ float hsm[768];
    __shared__ float red[8];
    __shared__ float stat[2];
    int b = blockIdx.x, tid = threadIdx.x;
    const float* xr = Xr + (size_t)b * NSEL * Dm;
    float v0 = xr[tid], v1 = xr[tid + 256], v2 = xr[tid + 512];
    float s = warp_sum(v0 + v1 + v2);
    if ((tid & 31) == 0) red[tid >> 5] = s;
    __syncthreads();
    if (tid < 8) {
        float r = red[tid];
        #pragma unroll
        for (int o = 4; o; o >>= 1) r += __shfl_xor_sync(0xFFu, r, o);
        if (tid == 0) stat[0] = r * (1.f / 768.f);
    }
    __syncthreads();
    float m = stat[0];
    float d0 = v0 - m, d1 = v1 - m, d2 = v2 - m;
    float q = warp_sum(d0 * d0 + d1 * d1 + d2 * d2);
    if ((tid & 31) == 0) red[tid >> 5] = q;
    __syncthreads();
    if (tid < 8) {
        float r = red[tid];
        #pragma unroll
        for (int o = 4; o; o >>= 1) r += __shfl_xor_sync(0xFFu, r, o);
        if (tid == 0) stat[1] = rsqrtf(r * (1.f / 768.f) + 1e-6f);
    }
    __syncthreads();
    float rs = stat[1];
    hsm[tid]       = d0 * rs * g[tid]       + bt[tid];
    hsm[tid + 256] = d1 * rs * g[tid + 256] + bt[tid + 256];
    hsm[tid + 512] = d2 * rs * g[tid + 512] + bt[tid + 512];
    __syncthreads();
    for (int c = 0; c < 10; c++) {
        float a = 0.f;
        for (int k = tid; k < 768; k += 256) a += hsm[k] * hw[k * 10 + c];
        a = warp_sum(a);
        if ((tid & 31) == 0) red[tid >> 5] = a;
        __syncthreads();
        if (tid == 0) {
            float r = 0.f;
            #pragma unroll
            for (int i = 0; i < 8; i++) r += red[i];
            out[b * 10 + c] = r + hb[c];
        }
        __syncthreads();
    }
}

// ---------------- host orchestration ----------------
extern "C" void kernel_launch(void* const* d_in, const int* in_sizes, int n_in,
                              void* d_out, int out_size) {
    const float* x        = (const float*)d_in[0];
    const float* patch_w  = (const float*)d_in[1];
    const float* patch_b  = (const float*)d_in[2];
    const float* cls_tok  = (const float*)d_in[3];
    const float* pos_emb  = (const float*)d_in[4];
    const float* ln1_g    = (const float*)d_in[5];
    const float* ln1_b    = (const float*)d_in[6];
    const float* qkv_w    = (const float*)d_in[7];
    const float* qkv_b    = (const float*)d_in[8];
    const float* proj_w   = (const float*)d_in[9];
    const float* proj_b   = (const float*)d_in[10];
    const float* ln2_g    = (const float*)d_in[11];
    const float* ln2_b    = (const float*)d_in[12];
    const float* fc1_w    = (const float*)d_in[13];
    const float* fc1_b    = (const float*)d_in[14];
    const float* fc2_w    = (const float*)d_in[15];
    const float* fc2_b    = (const float*)d_in[16];
    const float* sel_ln_g = (const float*)d_in[17];
    const float* sel_ln_b = (const float*)d_in[18];
    const float* sel_w1   = (const float*)d_in[19];
    const float* sel_b1   = (const float*)d_in[20];
    const float* sel_w2   = (const float*)d_in[21];
    const float* sel_b2   = (const float*)d_in[22];
    const float* norm_g   = (const float*)d_in[23];
    const float* norm_b   = (const float*)d_in[24];
    const float* head_w   = (const float*)d_in[25];
    const float* head_b   = (const float*)d_in[26];
    float* out = (float*)d_out;

    float *pX, *pH, *pQKV, *pScores, *pXr, *pF1f;
    float *pW32q, *pW32p, *pW32f1, *pW32f2;
    int* pIdx;
    __nv_bfloat16 *pAh, *pAl, *pF1h, *pF1l;
    __nv_bfloat16 *pWqkvh, *pWqkvl, *pWprojh, *pWprojl, *pW1h, *pW1l, *pW2h, *pW2l, *pPWh, *pPWl;
    cudaGetSymbolAddress((void**)&pX, g_X);
    cudaGetSymbolAddress((void**)&pH, g_Hbuf);
    cudaGetSymbolAddress((void**)&pQKV, g_QKV);
    cudaGetSymbolAddress((void**)&pScores, g_scores);
    cudaGetSymbolAddress((void**)&pIdx, g_idx);
    cudaGetSymbolAddress((void**)&pXr, g_Xr);
    cudaGetSymbolAddress((void**)&pF1f, g_F1f);
    cudaGetSymbolAddress((void**)&pAh, g_Ah);
    cudaGetSymbolAddress((void**)&pAl, g_Al);
    cudaGetSymbolAddress((void**)&pF1h, g_F1h);
    cudaGetSymbolAddress((void**)&pF1l, g_F1l);
    cudaGetSymbolAddress((void**)&pWqkvh, g_Wqkvh);
    cudaGetSymbolAddress((void**)&pWqkvl, g_Wqkvl);
    cudaGetSymbolAddress((void**)&pWprojh, g_Wprojh);
    cudaGetSymbolAddress((void**)&pWprojl, g_Wprojl);
    cudaGetSymbolAddress((void**)&pW1h, g_W1h);
    cudaGetSymbolAddress((void**)&pW1l, g_W1l);
    cudaGetSymbolAddress((void**)&pW2h, g_W2h);
    cudaGetSymbolAddress((void**)&pW2l, g_W2l);
    cudaGetSymbolAddress((void**)&pPWh, g_PWh);
    cudaGetSymbolAddress((void**)&pPWl, g_PWl);
    cudaGetSymbolAddress((void**)&pW32q, g_W32q);
    cudaGetSymbolAddress((void**)&pW32p, g_W32p);
    cudaGetSymbolAddress((void**)&pW32f1, g_W32f1);
    cudaGetSymbolAddress((void**)&pW32f2, g_W32f2);

    const int GEMM_SMEM = 2 * STAGE64;   // 73728
    const int TF_SMEM   = 2 * STAGEF;    // 73728
    cudaFuncSetAttribute(bgemm_kernel<0>, cudaFuncAttributeMaxDynamicSharedMemorySize, GEMM_SMEM);
    cudaFuncSetAttribute(bgemm_kernel<1>, cudaFuncAttributeMaxDynamicSharedMemorySize, GEMM_SMEM);
    cudaFuncSetAttribute(bgemm_kernel<2>, cudaFuncAttributeMaxDynamicSharedMemorySize, GEMM_SMEM);
    cudaFuncSetAttribute(tfgemm_kernel<0>, cudaFuncAttributeMaxDynamicSharedMemorySize, TF_SMEM);
    cudaFuncSetAttribute(tfgemm_kernel<1>, cudaFuncAttributeMaxDynamicSharedMemorySize, TF_SMEM);
    cudaFuncSetAttribute(tfgemm_kernel<2>, cudaFuncAttributeMaxDynamicSharedMemorySize, TF_SMEM);
    cudaFuncSetAttribute((const void*)attn_kernel<7, 0>,
                         cudaFuncAttributeMaxDynamicSharedMemorySize, 132 * 1024);
    cudaFuncSetAttribute((const void*)attn_kernel<3, 1>,
                         cudaFuncAttributeMaxDynamicSharedMemorySize, 132 * 1024);

    // weight conversion: warm -> bf16 hi/lo; refined -> tf32 transposed (K-permuted)
    dim3 ct(32, 8);
    convtrans_kernel<<<dim3(2304 / 32, 768 / 32, WARM), ct>>>(qkv_w, pWqkvh, pWqkvl, 768, 2304);
    convtrans_kernel<<<dim3(768 / 32, 768 / 32, WARM), ct>>>(proj_w, pWprojh, pWprojl, 768, 768);
    convtrans_kernel<<<dim3(3072 / 32, 768 / 32, WARM), ct>>>(fc1_w, pW1h, pW1l, 768, 3072);
    convtrans_kernel<<<dim3(768 / 32, 3072 / 32, WARM), ct>>>(fc2_w, pW2h, pW2l, 3072, 768);
    conv_patchw_kernel<<<(768 * 768 / 2 + 255) / 256, 256>>>(patch_w, pPWh, pPWl);
    convtrans_tf32_kernel<<<dim3(2304 / 32, 768 / 32, NREF), ct>>>(
        qkv_w + (size_t)WARM * 768 * 2304, pW32q, 768, 2304);
    convtrans_tf32_kernel<<<dim3(768 / 32, 768 / 32, NREF), ct>>>(
        proj_w + (size_t)WARM * 768 * 768, pW32p, 768, 768);
    convtrans_tf32_kernel<<<dim3(3072 / 32, 768 / 32, NREF), ct>>>(
        fc1_w + (size_t)WARM * 768 * 3072, pW32f1, 768, 3072);
    convtrans_tf32_kernel<<<dim3(768 / 32, 3072 / 32, NREF), ct>>>(
        fc2_w + (size_t)WARM * 3072 * 768, pW32f2, 3072, 768);

    // patch embed (bf16-3)
    im2col_kernel<<<Bb * 196, 256>>>(x, pAh, pAl);
    {
        dim3 grid(768 / 64, (Bb * 196 + 63) / 64);
        bgemm_kernel<0><<<grid, 128, GEMM_SMEM>>>(pAh, pAl, pPWh, pPWl, patch_b, nullptr,
                                                  pH, nullptr, nullptr, Bb * 196, 768, 768);
    }
    assemble_kernel<<<Bb * NTOK, 256>>>(pH, cls_tok, pos_emb, pX);

    for (int i = 0; i < DEPTH; i++) {
        const int N = (i < WARM) ? NTOK : NSEL;
        float* Xc = (i < WARM) ? pX : pXr;
        const int M = Bb * N;
        const int gy = (M + 63) / 64;
        dim3 gQKV(2304 / 64, gy), gD(768 / 64, gy), gMLP(3072 / 64, gy);
        size_t smem = ((size_t)N * 68 + (size_t)N * 64 + 8 * 512) * sizeof(float);

        if (i < WARM) {
            ln_kernel<0><<<M, 256>>>(Xc, ln1_g + (size_t)i * Dm, ln1_b + (size_t)i * Dm,
                                     pAh, pAl, nullptr);
            bgemm_kernel<0><<<gQKV, 128, GEMM_SMEM>>>(pAh, pAl,
                pWqkvh + (size_t)i * 2304 * 768, pWqkvl + (size_t)i * 2304 * 768,
                qkv_b + (size_t)i * 2304, nullptr, pQKV, nullptr, nullptr, M, 2304, 768);
            attn_kernel<7, 0><<<Bb * Hh, 256, smem>>>(pQKV, pAh, pAl, nullptr, N);
            bgemm_kernel<1><<<gD, 128, GEMM_SMEM>>>(pAh, pAl,
                pWprojh + (size_t)i * 768 * 768, pWprojl + (size_t)i * 768 * 768,
                proj_b + (size_t)i * 768, Xc, Xc, nullptr, nullptr, M, 768, 768);
            ln_kernel<0><<<M, 256>>>(Xc, ln2_g + (size_t)i * Dm, ln2_b + (size_t)i * Dm,
                                     pAh, pAl, nullptr);
            bgemm_kernel<2><<<gMLP, 128, GEMM_SMEM>>>(pAh, pAl,
                pW1h + (size_t)i * 3072 * 768, pW1l + (size_t)i * 3072 * 768,
                fc1_b + (size_t)i * 3072, nullptr, nullptr, pF1h, pF1l, M, 3072, 768);
            bgemm_kernel<1><<<gD, 128, GEMM_SMEM>>>(pF1h, pF1l,
                pW2h + (size_t)i * 768 * 3072, pW2l + (size_t)i * 768 * 3072,
                fc2_b + (size_t)i * 768, Xc, Xc, nullptr, nullptr, M, 768, 3072);
        } else {
            const int ri = i - WARM;
            ln_kernel<1><<<M, 256>>>(Xc, ln1_g + (size_t)i * Dm, ln1_b + (size_t)i * Dm,
                                     nullptr, nullptr, pH);
            tfgemm_kernel<0><<<gQKV, 128, TF_SMEM>>>(pH, pW32q + (size_t)ri * 2304 * 768,
                qkv_b + (size_t)i * 2304, nullptr, pQKV, M, 2304, 768);
            attn_kernel<3, 1><<<Bb * Hh, 256, smem>>>(pQKV, nullptr, nullptr, pH, N);
            tfgemm_kernel<1><<<gD, 128, TF_SMEM>>>(pH, pW32p + (size_t)ri * 768 * 768,
                proj_b + (size_t)i * 768, Xc, Xc, M, 768, 768);
            ln_kernel<1><<<M, 256>>>(Xc, ln2_g + (size_t)i * Dm, ln2_b + (size_t)i * Dm,
                                     nullptr, nullptr, pH);
            tfgemm_kernel<2><<<gMLP, 128, TF_SMEM>>>(pH, pW32f1 + (size_t)ri * 3072 * 768,
                fc1_b + (size_t)i * 3072, nullptr, pF1f, M, 3072, 768);
            tfgemm_kernel<1><<<gD, 128, TF_SMEM>>>(pF1f, pW32f2 + (size_t)ri * 768 * 3072,
                fc2_b + (size_t)i * 768, Xc, Xc, M, 768, 3072);
        }

        if (i == WARM - 1) {
            selector_kernel<<<Bb * NTOK, 128>>>(pX, sel_ln_g, sel_ln_b, sel_w1, sel_b1,
                                                sel_w2, sel_b2, pScores);
            topk_kernel<<<Bb, 256>>>(pScores, pIdx);
            gather_kernel<<<Bb * NSEL, 256>>>(pX, pIdx, pXr);
        }
    }

    head_kernel<<<Bb, 256>>>(pXr, norm_g, norm_b, head_w, head_b, out);
}

// round 17
// speedup vs baseline: 1.0901x; 1.0511x over previous
#include <cuda_runtime.h>
#include <cuda_bf16.h>
#include <math.h>

#define Dm 768
#define Hh 12
#define DEPTH 12
#define WARM 2
#define Kk 64
#define MLPD 3072
#define NTOK 197
#define NSEL 65
#define Bb 32
#define NREF (DEPTH - WARM)

// ---------------- scratch (device globals; no allocation) ----------------
__device__ __align__(16) float g_X[Bb * NTOK * Dm];
__device__ __align__(16) float g_Hbuf[Bb * NTOK * Dm];      // patch out / refined tf32 act
__device__ __align__(16) float g_QKV[Bb * NTOK * 3 * Dm];
__device__ float g_scores[Bb * NTOK];
__device__ int   g_idx[Bb * NSEL];
__device__ __align__(16) float g_Xr[Bb * NSEL * Dm];
__device__ __align__(16) float g_F1f[Bb * NSEL * MLPD];     // refined fc1 out (tf32, K-permuted)

__device__ __align__(16) __nv_bfloat16 g_Ah[Bb * NTOK * Dm];
__device__ __align__(16) __nv_bfloat16 g_Al[Bb * NTOK * Dm];
__device__ __align__(16) __nv_bfloat16 g_F1h[Bb * NTOK * MLPD];
__device__ __align__(16) __nv_bfloat16 g_F1l[Bb * NTOK * MLPD];

__device__ __align__(16) __nv_bfloat16 g_Wqkvh[WARM * 2304 * 768];
__device__ __align__(16) __nv_bfloat16 g_Wqkvl[WARM * 2304 * 768];
__device__ __align__(16) __nv_bfloat16 g_Wprojh[WARM * 768 * 768];
__device__ __align__(16) __nv_bfloat16 g_Wprojl[WARM * 768 * 768];
__device__ __align__(16) __nv_bfloat16 g_W1h[WARM * 3072 * 768];
__device__ __align__(16) __nv_bfloat16 g_W1l[WARM * 3072 * 768];
__device__ __align__(16) __nv_bfloat16 g_W2h[WARM * 768 * 3072];
__device__ __align__(16) __nv_bfloat16 g_W2l[WARM * 768 * 3072];
__device__ __align__(16) __nv_bfloat16 g_PWh[768 * 768];
__device__ __align__(16) __nv_bfloat16 g_PWl[768 * 768];

// refined tf32 weights (transposed [N,K], f32 containers, tf32-rounded, K-permuted)
__device__ __align__(16) float g_W32q[NREF * 2304 * 768];
__device__ __align__(16) float g_W32p[NREF * 768 * 768];
__device__ __align__(16) float g_W32f1[NREF * 3072 * 768];
__device__ __align__(16) float g_W32f2[NREF * 768 * 3072];

// ---------------- helpers ----------------
__device__ __forceinline__ float gelu_exact(float x) {
    return 0.5f * x * (1.0f + erff(x * 0.70710678118654752440f));
}
__device__ __forceinline__ float warp_sum(float v) {
    #pragma unroll
    for (int o = 16; o; o >>= 1) v += __shfl_xor_sync(0xFFFFFFFFu, v, o);
    return v;
}
__device__ __forceinline__ float warp_max(float v) {
    #pragma unroll
    for (int o = 16; o; o >>= 1) v = fmaxf(v, __shfl_xor_sync(0xFFFFFFFFu, v, o));
    return v;
}
__device__ __forceinline__ void split_store(__nv_bfloat16* ph, __nv_bfloat16* pl, float v) {
    __nv_bfloat16 hv = __float2bfloat16(v);
    *ph = hv;
    *pl = __float2bfloat16(v - __bfloat162float(hv));
}
__device__ __forceinline__ float to_tf32(float x) {
    unsigned u;
    asm("cvt.rna.tf32.f32 %0, %1;" : "=r"(u) : "f"(x));
    return __uint_as_float(u);
}
// K-label permutation within 8-groups: order [0,4,1,5,2,6,3,7]
__device__ __forceinline__ int permk(int k) {
    return (k & ~7) | (((k & 3) << 1) | ((k >> 2) & 1));
}
__device__ __forceinline__ unsigned smem_u32(const void* p) {
    unsigned a;
    asm("{ .reg .u64 t; cvta.to.shared.u64 t, %1; cvt.u32.u64 %0, t; }" : "=r"(a) : "l"(p));
    return a;
}
__device__ __forceinline__ void cp16(unsigned dst, const void* src, bool pred) {
    int sz = pred ? 16 : 0;
    asm volatile("cp.async.cg.shared.global [%0], [%1], 16, %2;\n"
                 :: "r"(dst), "l"(src), "r"(sz));
}
__device__ __forceinline__ void cp_commit() {
    asm volatile("cp.async.commit_group;\n" ::);
}
template<int NG>
__device__ __forceinline__ void cp_wait() {
    asm volatile("cp.async.wait_group %0;\n" :: "n"(NG));
}
__device__ __forceinline__ void ldsm4(unsigned* r, unsigned a) {
    asm volatile("ldmatrix.sync.aligned.m8n8.x4.shared.b16 {%0,%1,%2,%3}, [%4];\n"
                 : "=r"(r[0]), "=r"(r[1]), "=r"(r[2]), "=r"(r[3]) : "r"(a));
}
__device__ __forceinline__ void mma16816(float* c, const unsigned* a, const unsigned* b) {
    asm volatile(
        "mma.sync.aligned.m16n8k16.row.col.f32.bf16.bf16.f32 "
        "{%0,%1,%2,%3}, {%4,%5,%6,%7}, {%8,%9}, {%0,%1,%2,%3};\n"
        : "+f"(c[0]), "+f"(c[1]), "+f"(c[2]), "+f"(c[3])
        : "r"(a[0]), "r"(a[1]), "r"(a[2]), "r"(a[3]), "r"(b[0]), "r"(b[1]));
}
__device__ __forceinline__ void mma16808tf(float* c, const unsigned* a, const unsigned* b) {
    asm volatile(
        "mma.sync.aligned.m16n8k8.row.col.f32.tf32.tf32.f32 "
        "{%0,%1,%2,%3}, {%4,%5,%6,%7}, {%8,%9}, {%0,%1,%2,%3};\n"
        : "+f"(c[0]), "+f"(c[1]), "+f"(c[2]), "+f"(c[3])
        : "r"(a[0]), "r"(a[1]), "r"(a[2]), "r"(a[3]), "r"(b[0]), "r"(b[1]));
}

// ================= split-bf16 mma.sync GEMM, 64x64 tiles (warm + patch) =========
#define LDT 72
#define TILE64 (64 * LDT * 2)
#define STAGE64 (4 * TILE64)

__device__ __forceinline__ void load_stage(unsigned sbuf,
                                           const __nv_bfloat16* __restrict__ Sa_h,
                                           const __nv_bfloat16* __restrict__ Sa_l,
                                           const __nv_bfloat16* __restrict__ Sb_h,
                                           const __nv_bfloat16* __restrict__ Sb_l,
                                           int rowA, int Mlim, int rowB, int Nlim,
                                           int ldK, int k0, int tid) {
    const int ch = tid & 7, rr = tid >> 3;
    #pragma unroll
    for (int j = 0; j < 4; j++) {
        int r = j * 16 + rr;
        unsigned doff = (unsigned)(r * (LDT * 2) + ch * 16);
        {
            int gr = rowA + r;
            bool ok = gr < Mlim;
            int cr = ok ? gr : (Mlim - 1);
            size_t so = (size_t)cr * ldK + k0 + ch * 8;
            cp16(sbuf + doff, Sa_h + so, ok);
            cp16(sbuf + TILE64 + doff, Sa_l + so, ok);
        }
        {
            int gb = rowB + r;
            bool ok = gb < Nlim;
            int cb = ok ? gb : (Nlim - 1);
            size_t so = (size_t)cb * ldK + k0 + ch * 8;
            cp16(sbuf + 2 * TILE64 + doff, Sb_h + so, ok);
            cp16(sbuf + 3 * TILE64 + doff, Sb_l + so, ok);
        }
    }
}

template<int EPI>   // 0 bias; 1 bias+res; 2 bias+GELU->bf16 pair
__global__ void __launch_bounds__(128, 3)
bgemm_kernel(const __nv_bfloat16* __restrict__ Ah, const __nv_bfloat16* __restrict__ Al,
             const __nv_bfloat16* __restrict__ Bh, const __nv_bfloat16* __restrict__ Bl,
             const float* __restrict__ bias, const float* __restrict__ Cin,
             float* __restrict__ outF, __nv_bfloat16* __restrict__ outBh,
             __nv_bfloat16* __restrict__ outBl, int M, int N, int K) {
    extern __shared__ char smv[];
    const int tid = threadIdx.x;
    const int wid = tid >> 5, lane = tid & 31;
    const int blockRow = blockIdx.y << 6;
    const int blockCol = blockIdx.x << 6;
    const int wm = (wid >> 1) << 5;
    const int wn = (wid & 1) << 5;
    const unsigned sb = smem_u32(smv);

    float acc[2][4][4];
    #pragma unroll
    for (int i = 0; i < 2; i++)
        #pragma unroll
        for (int j = 0; j < 4; j++) {
            acc[i][j][0] = 0.f; acc[i][j][1] = 0.f; acc[i][j][2] = 0.f; acc[i][j][3] = 0.f;
        }

    const int T = K >> 6;
    load_stage(sb, Ah, Al, Bh, Bl, blockRow, M, blockCol, N, K, 0, tid);
    cp_commit();

    const int arow = (lane & 15);
    const int kofA = (lane >> 4) << 3;
    const int brow = ((lane >> 4) << 3) + (lane & 7);
    const int kofB = lane & 8;

    for (int kt = 0; kt < T; kt++) {
        if (kt + 1 < T) {
            load_stage(sb + (unsigned)((kt + 1) & 1) * STAGE64, Ah, Al, Bh, Bl,
                       blockRow, M, blockCol, N, K, (kt + 1) << 6, tid);
            cp_commit();
            cp_wait<1>();
        } else {
            cp_wait<0>();
        }
        __syncthreads();

        const unsigned bufb = sb + (unsigned)(kt & 1) * STAGE64;
        const unsigned aB = bufb + (unsigned)((wm + arow) * (LDT * 2));
        const unsigned bB = bufb + 2 * TILE64 + (unsigned)((wn + brow) * (LDT * 2));
        #pragma unroll
        for (int ks = 0; ks < 4; ks++) {
            const int kk = ks << 4;
            unsigned ah[2][4], al[2][4], bh[4][2], bl[4][2];
            #pragma unroll
            for (int mi = 0; mi < 2; mi++) {
                unsigned ad = aB + (unsigned)(mi * 16 * (LDT * 2) + (kk + kofA) * 2);
                ldsm4(ah[mi], ad);
                ldsm4(al[mi], ad + TILE64);
            }
            #pragma unroll
            for (int nj = 0; nj < 2; nj++) {
                unsigned bd = bB + (unsigned)(nj * 16 * (LDT * 2) + (kk + kofB) * 2);
                unsigned t0[4], t1[4];
                ldsm4(t0, bd);
                ldsm4(t1, bd + TILE64);
                bh[nj * 2][0] = t0[0]; bh[nj * 2][1] = t0[1];
                bh[nj * 2 + 1][0] = t0[2]; bh[nj * 2 + 1][1] = t0[3];
                bl[nj * 2][0] = t1[0]; bl[nj * 2][1] = t1[1];
                bl[nj * 2 + 1][0] = t1[2]; bl[nj * 2 + 1][1] = t1[3];
            }
            #pragma unroll
            for (int mi = 0; mi < 2; mi++)
                #pragma unroll
                for (int ni = 0; ni < 4; ni++) {
                    mma16816(acc[mi][ni], ah[mi], bh[ni]);
                    mma16816(acc[mi][ni], ah[mi], bl[ni]);
                    mma16816(acc[mi][ni], al[mi], bh[ni]);
                }
        }
        if (kt + 1 < T) __syncthreads();   // last iter: epilogue reads no smem
    }

    const int gid = lane >> 2, tig = lane & 3;
    #pragma unroll
    for (int mi = 0; mi < 2; mi++) {
        #pragma unroll
        for (int ni = 0; ni < 4; ni++) {
            const int gr0 = blockRow + wm + mi * 16 + gid;
            const int gc = blockCol + wn + ni * 8 + tig * 2;
            const float b0v = bias[gc], b1v = bias[gc + 1];
            #pragma unroll
            for (int hf = 0; hf < 2; hf++) {
                const int gr = gr0 + hf * 8;
                if (gr < M) {
                    float v0 = acc[mi][ni][hf * 2 + 0] + b0v;
                    float v1 = acc[mi][ni][hf * 2 + 1] + b1v;
                    if (EPI == 1) {
                        const float2 rv = *(const float2*)(Cin + (size_t)gr * N + gc);
                        v0 += rv.x; v1 += rv.y;
                    }
                    if (EPI == 2) {
                        v0 = gelu_exact(v0); v1 = gelu_exact(v1);
                        __nv_bfloat16 h0 = __float2bfloat16(v0);
                        __nv_bfloat16 h1 = __float2bfloat16(v1);
                        __nv_bfloat162 hp; hp.x = h0; hp.y = h1;
                        __nv_bfloat162 lp;
                        lp.x = __float2bfloat16(v0 - __bfloat162float(h0));
                        lp.y = __float2bfloat16(v1 - __bfloat162float(h1));
                        *(__nv_bfloat162*)(outBh + (size_t)gr * N + gc) = hp;
                        *(__nv_bfloat162*)(outBl + (size_t)gr * N + gc) = lp;
                    } else {
                        float2 o; o.x = v0; o.y = v1;
                        *(float2*)(outF + (size_t)gr * N + gc) = o;
                    }
                }
            }
        }
    }
}

// ================= single-MMA tf32 GEMM, 64x64 tiles, permuted-K float2 loads =========
#define LDF 72
#define TILEF (64 * LDF * 4)       // 18432 B
#define STAGEF (2 * TILEF)         // 36864 B

__device__ __forceinline__ void load_stage_f(unsigned sbuf,
                                             const float* __restrict__ Af,
                                             const float* __restrict__ Bf,
                                             int rowA, int Mlim, int rowB, int Nlim,
                                             int ldK, int k0, int tid) {
    #pragma unroll
    for (int i = 0; i < 8; i++) {
        int idx = tid + i * 128;
        int r = idx >> 4, ch = idx & 15;
        unsigned doff = (unsigned)(r * (LDF * 4) + ch * 16);
        {
            int gr = rowA + r;
            bool ok = gr < Mlim;
            int cr = ok ? gr : (Mlim - 1);
            cp16(sbuf + doff, Af + (size_t)cr * ldK + k0 + ch * 4, ok);
        }
        {
            int gb = rowB + r;
            bool ok = gb < Nlim;
            int cb = ok ? gb : (Nlim - 1);
            cp16(sbuf + TILEF + doff, Bf + (size_t)cb * ldK + k0 + ch * 4, ok);
        }
    }
}

template<int EPI>   // 0 bias->f32; 1 bias+res->f32; 2 bias+GELU->tf32 f32 (K-permuted out)
__global__ void __launch_bounds__(128, 3)
tfgemm_kernel(const float* __restrict__ A, const float* __restrict__ B,
              const float* __restrict__ bias, const float* __restrict__ Cin,
              float* __restrict__ outF, int M, int N, int K) {
    extern __shared__ char smv[];
    const int tid = threadIdx.x;
    const int wid = tid >> 5, lane = tid & 31;
    const int blockRow = blockIdx.y << 6;
    const int blockCol = blockIdx.x << 6;
    const int wm = (wid >> 1) << 5;
    const int wn = (wid & 1) << 5;
    const unsigned sb = smem_u32(smv);
    const float2* sm2 = (const float2*)smv;

    float acc[2][4][4];
    #pragma unroll
    for (int i = 0; i < 2; i++)
        #pragma unroll
        for (int j = 0; j < 4; j++) {
            acc[i][j][0] = 0.f; acc[i][j][1] = 0.f; acc[i][j][2] = 0.f; acc[i][j][3] = 0.f;
        }

    const int T = K >> 6;
    load_stage_f(sb, A, B, blockRow, M, blockCol, N, K, 0, tid);
    cp_commit();

    const int gid = lane >> 2, tig = lane & 3;

    for (int kt = 0; kt < T; kt++) {
        if (kt + 1 < T) {
            load_stage_f(sb + (unsigned)((kt + 1) & 1) * STAGEF, A, B,
                         blockRow, M, blockCol, N, K, (kt + 1) << 6, tid);
            cp_commit();
            cp_wait<1>();
        } else {
            cp_wait<0>();
        }
        __syncthreads();

        // float2 units: stage offset, B-tile offset, row stride LDF/2 = 36
        const unsigned bufw2 = (unsigned)(kt & 1) * (STAGEF / 8);
        #pragma unroll
        for (int ks = 0; ks < 8; ks++) {
            const int kk2 = ks << 2;   // k/2
            unsigned af[2][4], bf[4][2];
            #pragma unroll
            for (int mi = 0; mi < 2; mi++) {
                unsigned r0 = bufw2 + (unsigned)((wm + mi * 16 + gid) * 36 + kk2 + tig);
                float2 alo = sm2[r0];             // rows gid   : (k+tig, k+tig+4)
                float2 ahi = sm2[r0 + 4 * LDF];   // rows gid+8
                af[mi][0] = __float_as_uint(alo.x);
                af[mi][2] = __float_as_uint(alo.y);
                af[mi][1] = __float_as_uint(ahi.x);
                af[mi][3] = __float_as_uint(ahi.y);
            }
            #pragma unroll
            for (int ni = 0; ni < 4; ni++) {
                unsigned rb = bufw2 + (unsigned)(TILEF / 8) +
                              (unsigned)((wn + ni * 8 + gid) * 36 + kk2 + tig);
                float2 bv = sm2[rb];
                bf[ni][0] = __float_as_uint(bv.x);
                bf[ni][1] = __float_as_uint(bv.y);
            }
            #pragma unroll
            for (int mi = 0; mi < 2; mi++)
                #pragma unroll
                for (int ni = 0; ni < 4; ni++)
                    mma16808tf(acc[mi][ni], af[mi], bf[ni]);
        }
        if (kt + 1 < T) __syncthreads();   // last iter: epilogue reads no smem
    }

    #pragma unroll
    for (int mi = 0; mi < 2; mi++) {
        #pragma unroll
        for (int ni = 0; ni < 4; ni++) {
            const int gr0 = blockRow + wm + mi * 16 + gid;
            const int gc = blockCol + wn + ni * 8 + tig * 2;
            const float b0v = bias[gc], b1v = bias[gc + 1];
            #pragma unroll
            for (int hf = 0; hf < 2; hf++) {
                const int gr = gr0 + hf * 8;
                if (gr < M) {
                    float v0 = acc[mi][ni][hf * 2 + 0] + b0v;
                    float v1 = acc[mi][ni][hf * 2 + 1] + b1v;
                    if (EPI == 1) {
                        const float2 rv = *(const float2*)(Cin + (size_t)gr * N + gc);
                        v0 += rv.x; v1 += rv.y;
                    }
                    if (EPI == 2) {
                        v0 = to_tf32(gelu_exact(v0));
                        v1 = to_tf32(gelu_exact(v1));
                        outF[(size_t)gr * N + permk(gc)]     = v0;
                        outF[(size_t)gr * N + permk(gc + 1)] = v1;
                    } else {
                        float2 o; o.x = v0; o.y = v1;
                        *(float2*)(outF + (size_t)gr * N + gc) = o;
                    }
                }
            }
        }
    }
}

// ---------------- weight converts ----------------
__global__ void convtrans_kernel(const float* __restrict__ W, __nv_bfloat16* __restrict__ Wh,
                                 __nv_bfloat16* __restrict__ Wl, int K, int N) {
    __shared__ float ts[32][33];
    const int l = blockIdx.z;
    const size_t off = (size_t)l * K * N;
    const int kb = blockIdx.y << 5, nb = blockIdx.x << 5;
    #pragma unroll
    for (int j = 0; j < 4; j++)
        ts[threadIdx.y + 8 * j][threadIdx.x] =
            W[off + (size_t)(kb + threadIdx.y + 8 * j) * N + nb + threadIdx.x];
    __syncthreads();
    const int tid = threadIdx.y * 32 + threadIdx.x;
    const int c2 = tid & 15, r0 = tid >> 4;
    #pragma unroll
    for (int j = 0; j < 2; j++) {
        int r = r0 + 16 * j;
        float v0 = ts[2 * c2][r], v1 = ts[2 * c2 + 1][r];
        __nv_bfloat16 h0 = __float2bfloat16(v0), h1 = __float2bfloat16(v1);
        __nv_bfloat162 hp; hp.x = h0; hp.y = h1;
        __nv_bfloat162 lp;
        lp.x = __float2bfloat16(v0 - __bfloat162float(h0));
        lp.y = __float2bfloat16(v1 - __bfloat162float(h1));
        size_t di = off + (size_t)(nb + r) * K + kb + 2 * c2;
        *(__nv_bfloat162*)(Wh + di) = hp;
        *(__nv_bfloat162*)(Wl + di) = lp;
    }
}

// tf32 transpose-convert with K-permutation
__global__ void convtrans_tf32_kernel(const float* __restrict__ W, float* __restrict__ Wt,
                                      int K, int N) {
    __shared__ float ts[32][33];
    const int l = blockIdx.z;
    const size_t off = (size_t)l * K * N;
    const int kb = blockIdx.y << 5, nb = blockIdx.x << 5;
    #pragma unroll
    for (int j = 0; j < 4; j++)
        ts[threadIdx.y + 8 * j][threadIdx.x] =
            W[off + (size_t)(kb + threadIdx.y + 8 * j) * N + nb + threadIdx.x];
    __syncthreads();
    const int tid = threadIdx.y * 32 + threadIdx.x;
    const int c2 = tid & 15, r0 = tid >> 4;
    #pragma unroll
    for (int j = 0; j < 2; j++) {
        int r = r0 + 16 * j;
        size_t rbase = off + (size_t)(nb + r) * K;
        Wt[rbase + permk(kb + 2 * c2)]     = to_tf32(ts[2 * c2][r]);
        Wt[rbase + permk(kb + 2 * c2 + 1)] = to_tf32(ts[2 * c2 + 1][r]);
    }
}

__global__ void conv_patchw_kernel(const float* __restrict__ W, __nv_bfloat16* __restrict__ Wh,
                                   __nv_bfloat16* __restrict__ Wl) {
    int i = blockIdx.x * 256 + threadIdx.x;
    if (i < 768 * 768 / 2) {
        float2 v = *(const float2*)(W + 2 * i);
        __nv_bfloat16 h0 = __float2bfloat16(v.x), h1 = __float2bfloat16(v.y);
        __nv_bfloat162 hp; hp.x = h0; hp.y = h1;
        __nv_bfloat162 lp;
        lp.x = __float2bfloat16(v.x - __bfloat162float(h0));
        lp.y = __float2bfloat16(v.y - __bfloat162float(h1));
        *(__nv_bfloat162*)(Wh + 2 * i) = hp;
        *(__nv_bfloat162*)(Wl + 2 * i) = lp;
    }
}

// ---------------- im2col / assemble ----------------
__global__ void im2col_kernel(const float* __restrict__ x, __nv_bfloat16* __restrict__ Ph,
                              __nv_bfloat16* __restrict__ Pl) {
    int t = blockIdx.x;
    int b = t / 196, p = t % 196;
    int py = p / 14, px = p % 14;
    for (int d = threadIdx.x; d < Dm; d += 256) {
        int c = d >> 8, r = (d >> 4) & 15, col = d & 15;
        float v = x[(((size_t)b * 3 + c) * 224 + py * 16 + r) * 224 + px * 16 + col];
        split_store(Ph + (size_t)t * Dm + d, Pl + (size_t)t * Dm + d, v);
    }
}

__global__ void assemble_kernel(const float* __restrict__ P, const float* __restrict__ cls,
                                const float* __restrict__ pos, float* __restrict__ X) {
    int t = blockIdx.x;
    int b = t / NTOK, n = t % NTOK;
    float* xr = X + (size_t)t * Dm;
    const float* pr = pos + (size_t)n * Dm;
    if (n == 0) {
        for (int d = threadIdx.x; d < Dm; d += 256) xr[d] = cls[d] + pr[d];
    } else {
        const float* pp = P + ((size_t)(b * 196 + n - 1)) * Dm;
        for (int d = threadIdx.x; d < Dm; d += 256) xr[d] = pp[d] + pr[d];
    }
}

// ---------------- LayerNorm variants ----------------
template<int TF>    // 0: bf16 hi/lo out ; 1: tf32 f32 out (K-permuted)
__global__ void ln_kernel(const float* __restrict__ X, const float* __restrict__ g,
                          const float* __restrict__ bt, __nv_bfloat16* __restrict__ Yh,
                          __nv_bfloat16* __restrict__ Yl, float* __restrict__ Yf) {
    __shared__ float red[8];
    __shared__ float stat[2];
    int t = blockIdx.x, tid = threadIdx.x;
    const float* xr = X + (size_t)t * Dm;
    float v0 = xr[tid], v1 = xr[tid + 256], v2 = xr[tid + 512];
    float s = warp_sum(v0 + v1 + v2);
    if ((tid & 31) == 0) red[tid >> 5] = s;
    __syncthreads();
    if (tid < 8) {
        float r = red[tid];
        #pragma unroll
        for (int o = 4; o; o >>= 1) r += __shfl_xor_sync(0xFFu, r, o);
        if (tid == 0) stat[0] = r * (1.f / 768.f);
    }
    __syncthreads();
    float m = stat[0];
    float d0 = v0 - m, d1 = v1 - m, d2 = v2 - m;
    float q = warp_sum(d0 * d0 + d1 * d1 + d2 * d2);
    if ((tid & 31) == 0) red[tid >> 5] = q;
    __syncthreads();
    if (tid < 8) {
        float r = red[tid];
        #pragma unroll
        for (int o = 4; o; o >>= 1) r += __shfl_xor_sync(0xFFu, r, o);
        if (tid == 0) stat[1] = rsqrtf(r * (1.f / 768.f) + 1e-6f);
    }
    __syncthreads();
    float rs = stat[1];
    size_t base = (size_t)t * Dm;
    float y0 = d0 * rs * g[tid]       + bt[tid];
    float y1 = d1 * rs * g[tid + 256] + bt[tid + 256];
    float y2 = d2 * rs * g[tid + 512] + bt[tid + 512];
    if (TF) {
        Yf[base + permk(tid)]       = to_tf32(y0);
        Yf[base + permk(tid + 256)] = to_tf32(y1);
        Yf[base + permk(tid + 512)] = to_tf32(y2);
    } else {
        split_store(Yh + base + tid,       Yl + base + tid,       y0);
        split_store(Yh + base + tid + 256, Yl + base + tid + 256, y1);
        split_store(Yh + base + tid + 512, Yl + base + tid + 512, y2);
    }
}

// ---------------- fused attention, 8 queries per warp ----------------
template<int NJ, int TF>
__global__ void __launch_bounds__(256)
attn_kernel(const float* __restrict__ QKV, __nv_bfloat16* __restrict__ Oh,
            __nv_bfloat16* __restrict__ Ol, float* __restrict__ Of, int N) {
    extern __shared__ float smf[];
    float* Ks = smf;
    float* Vs = Ks + N * 68;
    float* qs = Vs + N * 64;
    int b = blockIdx.x / Hh, hd = blockIdx.x % Hh;
    int tid = threadIdx.x, w = tid >> 5, lane = tid & 31;
    const float* base = QKV + (size_t)b * N * (3 * Dm);
    for (int idx = tid; idx < N * 64; idx += 256) {
        int n = idx >> 6, d = idx & 63;
        Ks[n * 68 + d] = base[(size_t)n * (3 * Dm) + Dm + hd * 64 + d];
        Vs[idx]        = base[(size_t)n * (3 * Dm) + 2 * Dm + hd * 64 + d];
    }
    __syncthreads();
    float* qw = qs + w * 512;
    for (int qt = w * 8; qt < N; qt += 64) {
        #pragma unroll
        for (int qi = 0; qi < 8; qi++) {
            int q = qt + qi;
            if (q < N) {
                const float* qp = base + (size_t)q * (3 * Dm) + hd * 64;
                qw[qi * 64 + lane]      = qp[lane]      * 0.125f;
                qw[qi * 64 + lane + 32] = qp[lane + 32] * 0.125f;
            }
        }
        __syncwarp();
        float s[8][NJ];
        #pragma unroll
        for (int qi = 0; qi < 8; qi++)
            #pragma unroll
            for (int jj = 0; jj < NJ; jj++) s[qi][jj] = -3e38f;
        #pragma unroll
        for (int jj = 0; jj < NJ; jj++) {
            int j = jj * 32 + lane;
            if (j < N) {
                const float4* k4 = (const float4*)(Ks + j * 68);
                float acc[8];
                #pragma unroll
                for (int qi = 0; qi < 8; qi++) acc[qi] = 0.f;
                #pragma unroll
                for (int d = 0; d < 16; d++) {
                    float4 kv = k4[d];
                    #pragma unroll
                    for (int qi = 0; qi < 8; qi++) {
                        float4 qv = ((const float4*)(qw + qi * 64))[d];
                        acc[qi] += qv.x * kv.x + qv.y * kv.y + qv.z * kv.z + qv.w * kv.w;
                    }
                }
                #pragma unroll
                for (int qi = 0; qi < 8; qi++) s[qi][jj] = acc[qi];
            }
        }
        float inv[8];
        #pragma unroll
        for (int qi = 0; qi < 8; qi++) {
            float m = -3e38f;
            #pragma unroll
            for (int jj = 0; jj < NJ; jj++) m = fmaxf(m, s[qi][jj]);
            m = warp_max(m);
            float sum = 0.f;
            #pragma unroll
            for (int jj = 0; jj < NJ; jj++) {
                float e = expf(s[qi][jj] - m);
                s[qi][jj] = e;
                sum += e;
            }
            sum = warp_sum(sum);
            inv[qi] = 1.f / sum;
        }
        float a0[8], a1[8];
        #pragma unroll
        for (int qi = 0; qi < 8; qi++) { a0[qi] = 0.f; a1[qi] = 0.f; }
        #pragma unroll
        for (int jj = 0; jj < NJ; jj++) {
            int jb = jj * 32;
            int lim = N - jb; if (lim > 32) lim = 32;
            for (int src = 0; src < lim; src++) {
                int j = jb + src;
                float v0 = Vs[j * 64 + lane];
                float v1 = Vs[j * 64 + lane + 32];
                #pragma unroll
                for (int qi = 0; qi < 8; qi++) {
                    float p = __shfl_sync(0xFFFFFFFFu, s[qi][jj], src);
                    a0[qi] += p * v0;
                    a1[qi] += p * v1;
                }
            }
        }
        #pragma unroll
        for (int qi = 0; qi < 8; qi++) {
            int q = qt + qi;
            if (q < N) {
                size_t oo = ((size_t)(b * N + q)) * Dm;
                int c0 = hd * 64 + lane;
                if (TF) {
                    Of[oo + permk(c0)]      = to_tf32(a0[qi] * inv[qi]);
                    Of[oo + permk(c0 + 32)] = to_tf32(a1[qi] * inv[qi]);
                } else {
                    split_store(Oh + oo + c0,      Ol + oo + c0,      a0[qi] * inv[qi]);
                    split_store(Oh + oo + c0 + 32, Ol + oo + c0 + 32, a1[qi] * inv[qi]);
                }
            }
        }
        __syncwarp();
    }
}

// ---------------- token selector ----------------
__global__ void selector_kernel(const float* __restrict__ X, const float* __restrict__ g,
                                const float* __restrict__ bt, const float* __restrict__ w1,
                                const float* __restrict__ b1, const float* __restrict__ w2,
                                const float* __restrict__ b2, float* __restrict__ scores) {
    __shared__ float hsm[768];
    __shared__ float red[4];
    __shared__ float stat[2];
    int t = blockIdx.x, tid = threadIdx.x;
    const float* xr = X + (size_t)t * Dm;
    float v[6];
    #pragma unroll
    for (int i = 0; i < 6; i++) v[i] = xr[tid + i * 128];
    float s = 0.f;
    #pragma unroll
    for (int i = 0; i < 6; i++) s += v[i];
    s = warp_sum(s);
    if ((tid & 31) == 0) red[tid >> 5] = s;
    __syncthreads();
    if (tid == 0) stat[0] = (red[0] + red[1] + red[2] + red[3]) * (1.f / 768.f);
    __syncthreads();
    float m = stat[0], q = 0.f;
    #pragma unroll
    for (int i = 0; i < 6; i++) { float d = v[i] - m; q += d * d; }
    q = warp_sum(q);
    if ((tid & 31) == 0) red[tid >> 5] = q;
    __syncthreads();
    if (tid == 0) stat[1] = rsqrtf((red[0] + red[1] + red[2] + red[3]) * (1.f / 768.f) + 1e-6f);
    __syncthreads();
    float rs = stat[1];
    #pragma unroll
    for (int i = 0; i < 6; i++)
        hsm[tid + i * 128] = (v[i] - m) * rs * g[tid + i * 128] + bt[tid + i * 128];
    __syncthreads();
    float acc = b1[tid];
    for (int k = 0; k < 768; k++) acc += hsm[k] * w1[k * 128 + tid];
    float gl = gelu_exact(acc) * w2[tid];
    gl = warp_sum(gl);
    if ((tid & 31) == 0) red[tid >> 5] = gl;
    __syncthreads();
    if (tid == 0) scores[t] = red[0] + red[1] + red[2] + red[3] + b2[0];
}

// ---------------- top-64 per batch ----------------
__global__ void topk_kernel(const float* __restrict__ scores, int* __restrict__ idx) {
    __shared__ float sv[196];
    __shared__ float rv[256];
    __shared__ int ri[256];
    int b = blockIdx.x, tid = threadIdx.x;
    if (tid < 196) sv[tid] = scores[b * NTOK + 1 + tid];
    if (tid == 0) idx[b * NSEL] = 0;
    __syncthreads();
    for (int it = 0; it < Kk; it++) {
        rv[tid] = (tid < 196) ? sv[tid] : -3e38f;
        ri[tid] = tid;
        __syncthreads();
        for (int s2 = 128; s2 > 0; s2 >>= 1) {
            if (tid < s2) {
                if (rv[tid + s2] > rv[tid] ||
                    (rv[tid + s2] == rv[tid] && ri[tid + s2] < ri[tid])) {
                    rv[tid] = rv[tid + s2];
                    ri[tid] = ri[tid + s2];
                }
            }
            __syncthreads();
        }
        if (tid == 0) { idx[b * NSEL + 1 + it] = ri[0] + 1; sv[ri[0]] = -3e38f; }
        __syncthreads();
    }
}

__global__ void gather_kernel(const float* __restrict__ X, const int* __restrict__ idx,
                              float* __restrict__ Xr) {
    int t = blockIdx.x;
    int b = t / NSEL;
    int src = idx[t];
    const float* s = X + ((size_t)b * NTOK + src) * Dm;
    float* d = Xr + (size_t)t * Dm;
    for (int i = threadIdx.x; i < Dm; i += 256) d[i] = s[i];
}

// ---------------- final LN(CLS) + head ----------------
__global__ void head_kernel(const float* __restrict__ Xr, const float* __restrict__ g,
                            const float* __restrict__ bt, const float* __restrict__ hw,
                            const float* __restrict__ hb, float* __restrict__ out) {
    __shared__ float hsm[768];
    __shared__ float red[8];
    __shared__ float stat[2];
    int b = blockIdx.x, tid = threadIdx.x;
    const float* xr = Xr + (size_t)b * NSEL * Dm;
    float v0 = xr[tid], v1 = xr[tid + 256], v2 = xr[tid + 512];
    float s = warp_sum(v0 + v1 + v2);
    if ((tid & 31) == 0) red[tid >> 5] = s;
    __syncthreads();
    if (tid < 8) {
        float r = red[tid];
        #pragma unroll
        for (int o = 4; o; o >>= 1) r += __shfl_xor_sync(0xFFu, r, o);
        if (tid == 0) stat[0] = r * (1.f / 768.f);
    }
    __syncthreads();
    float m = stat[0];
    float d0 = v0 - m, d1 = v1 - m, d2 = v2 - m;
    float q = warp_sum(d0 * d0 + d1 * d1 + d2 * d2);
    if ((tid & 31) == 0) red[tid >> 5] = q;
    __syncthreads();
    if (tid < 8) {
        float r = red[tid];
        #pragma unroll
        for (int o = 4; o; o >>= 1) r += __shfl_xor_sync(0xFFu, r, o);
        if (tid == 0) stat[1] = rsqrtf(r * (1.f / 768.f) + 1e-6f);
    }
    __syncthreads();
    float rs = stat[1];
    hsm[tid]       = d0 * rs * g[tid]       + bt[tid];
    hsm[tid + 256] = d1 * rs * g[tid + 256] + bt[tid + 256];
    hsm[tid + 512] = d2 * rs * g[tid + 512] + bt[tid + 512];
    __syncthreads();
    for (int c = 0; c < 10; c++) {
        float a = 0.f;
        for (int k = tid; k < 768; k += 256) a += hsm[k] * hw[k * 10 + c];
        a = warp_sum(a);
        if ((tid & 31) == 0) red[tid >> 5] = a;
        __syncthreads();
        if (tid == 0) {
            float r = 0.f;
            #pragma unroll
            for (int i = 0; i < 8; i++) r += red[i];
            out[b * 10 + c] = r + hb[c];
        }
        __syncthreads();
    }
}

// ---------------- host orchestration ----------------
extern "C" void kernel_launch(void* const* d_in, const int* in_sizes, int n_in,
                              void* d_out, int out_size) {
    const float* x        = (const float*)d_in[0];
    const float* patch_w  = (const float*)d_in[1];
    const float* patch_b  = (const float*)d_in[2];
    const float* cls_tok  = (const float*)d_in[3];
    const float* pos_emb  = (const float*)d_in[4];
    const float* ln1_g    = (const float*)d_in[5];
    const float* ln1_b    = (const float*)d_in[6];
    const float* qkv_w    = (const float*)d_in[7];
    const float* qkv_b    = (const float*)d_in[8];
    const float* proj_w   = (const float*)d_in[9];
    const float* proj_b   = (const float*)d_in[10];
    const float* ln2_g    = (const float*)d_in[11];
    const float* ln2_b    = (const float*)d_in[12];
    const float* fc1_w    = (const float*)d_in[13];
    const float* fc1_b    = (const float*)d_in[14];
    const float* fc2_w    = (const float*)d_in[15];
    const float* fc2_b    = (const float*)d_in[16];
    const float* sel_ln_g = (const float*)d_in[17];
    const float* sel_ln_b = (const float*)d_in[18];
    const float* sel_w1   = (const float*)d_in[19];
    const float* sel_b1   = (const float*)d_in[20];
    const float* sel_w2   = (const float*)d_in[21];
    const float* sel_b2   = (const float*)d_in[22];
    const float* norm_g   = (const float*)d_in[23];
    const float* norm_b   = (const float*)d_in[24];
    const float* head_w   = (const float*)d_in[25];
    const float* head_b   = (const float*)d_in[26];
    float* out = (float*)d_out;

    float *pX, *pH, *pQKV, *pScores, *pXr, *pF1f;
    float *pW32q, *pW32p, *pW32f1, *pW32f2;
    int* pIdx;
    __nv_bfloat16 *pAh, *pAl, *pF1h, *pF1l;
    __nv_bfloat16 *pWqkvh, *pWqkvl, *pWprojh, *pWprojl, *pW1h, *pW1l, *pW2h, *pW2l, *pPWh, *pPWl;
    cudaGetSymbolAddress((void**)&pX, g_X);
    cudaGetSymbolAddress((void**)&pH, g_Hbuf);
    cudaGetSymbolAddress((void**)&pQKV, g_QKV);
    cudaGetSymbolAddress((void**)&pScores, g_scores);
    cudaGetSymbolAddress((void**)&pIdx, g_idx);
    cudaGetSymbolAddress((void**)&pXr, g_Xr);
    cudaGetSymbolAddress((void**)&pF1f, g_F1f);
    cudaGetSymbolAddress((void**)&pAh, g_Ah);
    cudaGetSymbolAddress((void**)&pAl, g_Al);
    cudaGetSymbolAddress((void**)&pF1h, g_F1h);
    cudaGetSymbolAddress((void**)&pF1l, g_F1l);
    cudaGetSymbolAddress((void**)&pWqkvh, g_Wqkvh);
    cudaGetSymbolAddress((void**)&pWqkvl, g_Wqkvl);
    cudaGetSymbolAddress((void**)&pWprojh, g_Wprojh);
    cudaGetSymbolAddress((void**)&pWprojl, g_Wprojl);
    cudaGetSymbolAddress((void**)&pW1h, g_W1h);
    cudaGetSymbolAddress((void**)&pW1l, g_W1l);
    cudaGetSymbolAddress((void**)&pW2h, g_W2h);
    cudaGetSymbolAddress((void**)&pW2l, g_W2l);
    cudaGetSymbolAddress((void**)&pPWh, g_PWh);
    cudaGetSymbolAddress((void**)&pPWl, g_PWl);
    cudaGetSymbolAddress((void**)&pW32q, g_W32q);
    cudaGetSymbolAddress((void**)&pW32p, g_W32p);
    cudaGetSymbolAddress((void**)&pW32f1, g_W32f1);
    cudaGetSymbolAddress((void**)&pW32f2, g_W32f2);

    const int GEMM_SMEM = 2 * STAGE64;   // 73728
    const int TF_SMEM   = 2 * STAGEF;    // 73728
    cudaFuncSetAttribute(bgemm_kernel<0>, cudaFuncAttributeMaxDynamicSharedMemorySize, GEMM_SMEM);
    cudaFuncSetAttribute(bgemm_kernel<1>, cudaFuncAttributeMaxDynamicSharedMemorySize, GEMM_SMEM);
    cudaFuncSetAttribute(bgemm_kernel<2>, cudaFuncAttributeMaxDynamicSharedMemorySize, GEMM_SMEM);
    cudaFuncSetAttribute(tfgemm_kernel<0>, cudaFuncAttributeMaxDynamicSharedMemorySize, TF_SMEM);
    cudaFuncSetAttribute(tfgemm_kernel<1>, cudaFuncAttributeMaxDynamicSharedMemorySize, TF_SMEM);
    cudaFuncSetAttribute(tfgemm_kernel<2>, cudaFuncAttributeMaxDynamicSharedMemorySize, TF_SMEM);
    cudaFuncSetAttribute((const void*)attn_kernel<7, 0>,
                         cudaFuncAttributeMaxDynamicSharedMemorySize, 132 * 1024);
    cudaFuncSetAttribute((const void*)attn_kernel<3, 1>,
                         cudaFuncAttributeMaxDynamicSharedMemorySize, 132 * 1024);

    // weight conversion: warm -> bf16 hi/lo; refined -> tf32 transposed (K-permuted)
    dim3 ct(32, 8);
    convtrans_kernel<<<dim3(2304 / 32, 768 / 32, WARM), ct>>>(qkv_w, pWqkvh, pWqkvl, 768, 2304);
    convtrans_kernel<<<dim3(768 / 32, 768 / 32, WARM), ct>>>(proj_w, pWprojh, pWprojl, 768, 768);
    convtrans_kernel<<<dim3(3072 / 32, 768 / 32, WARM), ct>>>(fc1_w, pW1h, pW1l, 768, 3072);
    convtrans_kernel<<<dim3(768 / 32, 3072 / 32, WARM), ct>>>(fc2_w, pW2h, pW2l, 3072, 768);
    conv_patchw_kernel<<<(768 * 768 / 2 + 255) / 256, 256>>>(patch_w, pPWh, pPWl);
    convtrans_tf32_kernel<<<dim3(2304 / 32, 768 / 32, NREF), ct>>>(
        qkv_w + (size_t)WARM * 768 * 2304, pW32q, 768, 2304);
    convtrans_tf32_kernel<<<dim3(768 / 32, 768 / 32, NREF), ct>>>(
        proj_w + (size_t)WARM * 768 * 768, pW32p, 768, 768);
    convtrans_tf32_kernel<<<dim3(3072 / 32, 768 / 32, NREF), ct>>>(
        fc1_w + (size_t)WARM * 768 * 3072, pW32f1, 768, 3072);
    convtrans_tf32_kernel<<<dim3(768 / 32, 3072 / 32, NREF), ct>>>(
        fc2_w + (size_t)WARM * 3072 * 768, pW32f2, 3072, 768);

    // patch embed (bf16-3)
    im2col_kernel<<<Bb * 196, 256>>>(x, pAh, pAl);
    {
        dim3 grid(768 / 64, (Bb * 196 + 63) / 64);
        bgemm_kernel<0><<<grid, 128, GEMM_SMEM>>>(pAh, pAl, pPWh, pPWl, patch_b, nullptr,
                                                  pH, nullptr, nullptr, Bb * 196, 768, 768);
    }
    assemble_kernel<<<Bb * NTOK, 256>>>(pH, cls_tok, pos_emb, pX);

    for (int i = 0; i < DEPTH; i++) {
        const int N = (i < WARM) ? NTOK : NSEL;
        float* Xc = (i < WARM) ? pX : pXr;
        const int M = Bb * N;
        const int gy = (M + 63) / 64;
        dim3 gQKV(2304 / 64, gy), gD(768 / 64, gy), gMLP(3072 / 64, gy);
        size_t smem = ((size_t)N * 68 + (size_t)N * 64 + 8 * 512) * sizeof(float);

        if (i < WARM) {
            ln_kernel<0><<<M, 256>>>(Xc, ln1_g + (size_t)i * Dm, ln1_b + (size_t)i * Dm,
                                     pAh, pAl, nullptr);
            bgemm_kernel<0><<<gQKV, 128, GEMM_SMEM>>>(pAh, pAl,
                pWqkvh + (size_t)i * 2304 * 768, pWqkvl + (size_t)i * 2304 * 768,
                qkv_b + (size_t)i * 2304, nullptr, pQKV, nullptr, nullptr, M, 2304, 768);
            attn_kernel<7, 0><<<Bb * Hh, 256, smem>>>(pQKV, pAh, pAl, nullptr, N);
            bgemm_kernel<1><<<gD, 128, GEMM_SMEM>>>(pAh, pAl,
                pWprojh + (size_t)i * 768 * 768, pWprojl + (size_t)i * 768 * 768,
                proj_b + (size_t)i * 768, Xc, Xc, nullptr, nullptr, M, 768, 768);
            ln_kernel<0><<<M, 256>>>(Xc, ln2_g + (size_t)i * Dm, ln2_b + (size_t)i * Dm,
                                     pAh, pAl, nullptr);
            bgemm_kernel<2><<<gMLP, 128, GEMM_SMEM>>>(pAh, pAl,
                pW1h + (size_t)i * 3072 * 768, pW1l + (size_t)i * 3072 * 768,
                fc1_b + (size_t)i * 3072, nullptr, nullptr, pF1h, pF1l, M, 3072, 768);
            bgemm_kernel<1><<<gD, 128, GEMM_SMEM>>>(pF1h, pF1l,
                pW2h + (size_t)i * 768 * 3072, pW2l + (size_t)i * 768 * 3072,
                fc2_b + (size_t)i * 768, Xc, Xc, nullptr, nullptr, M, 768, 3072);
        } else {
            const int ri = i - WARM;
            ln_kernel<1><<<M, 256>>>(Xc, ln1_g + (size_t)i * Dm, ln1_b + (size_t)i * Dm,
                                     nullptr, nullptr, pH);
            tfgemm_kernel<0><<<gQKV, 128, TF_SMEM>>>(pH, pW32q + (size_t)ri * 2304 * 768,
                qkv_b + (size_t)i * 2304, nullptr, pQKV, M, 2304, 768);
            attn_kernel<3, 1><<<Bb * Hh, 256, smem>>>(pQKV, nullptr, nullptr, pH, N);
            tfgemm_kernel<1><<<gD, 128, TF_SMEM>>>(pH, pW32p + (size_t)ri * 768 * 768,
                proj_b + (size_t)i * 768, Xc, Xc, M, 768, 768);
            ln_kernel<1><<<M, 256>>>(Xc, ln2_g + (size_t)i * Dm, ln2_b + (size_t)i * Dm,
                                     nullptr, nullptr, pH);
            tfgemm_kernel<2><<<gMLP, 128, TF_SMEM>>>(pH, pW32f1 + (size_t)ri * 3072 * 768,
                fc1_b + (size_t)i * 3072, nullptr, pF1f, M, 3072, 768);
            tfgemm_kernel<1><<<gD, 128, TF_SMEM>>>(pF1f, pW32f2 + (size_t)ri * 768 * 3072,
                fc2_b + (size_t)i * 768, Xc, Xc, M, 768, 3072);
        }

        if (i == WARM - 1) {
            selector_kernel<<<Bb * NTOK, 128>>>(pX, sel_ln_g, sel_ln_b, sel_w1, sel_b1,
                                                sel_w2, sel_b2, pScores);
            topk_kernel<<<Bb, 256>>>(pScores, pIdx);
            gather_kernel<<<Bb * NSEL, 256>>>(pX, pIdx, pXr);
        }
    }

    head_kernel<<<Bb, 256>>>(pXr, norm_g, norm_b, head_w, head_b, out);
}